// round 14
// baseline (speedup 1.0000x reference)
#include <cuda_runtime.h>
#include <cuda_bf16.h>
#include <math.h>

#define BB 2
#define NN 4096
#define DD 64
#define HH 256
#define KK 16
#define NPTS (BB*NN)
#define ATTN_GRID 148
#define PTS 8               // points per iteration
#define ROWS 128            // PTS * KK rows
#define H2P 36              // packed bf16x2 row stride (u32)
#define SCP 65              // scores row stride

#define KNN_CAP 128
#define BIGD 3.0e38f

typedef unsigned long long u64;
typedef unsigned int u32;

// split two fp32 into packed bf16x2 hi and lo parts (x0 -> low half)
__device__ __forceinline__ void split2(float x0, float x1, u32& hi, u32& lo) {
    __nv_bfloat16 h0 = __float2bfloat16_rn(x0);
    __nv_bfloat16 h1 = __float2bfloat16_rn(x1);
    __nv_bfloat16 l0 = __float2bfloat16_rn(x0 - __bfloat162float(h0));
    __nv_bfloat16 l1 = __float2bfloat16_rn(x1 - __bfloat162float(h1));
    hi = (u32)*(unsigned short*)&h0 | ((u32)*(unsigned short*)&h1 << 16);
    lo = (u32)*(unsigned short*)&l0 | ((u32)*(unsigned short*)&l1 << 16);
}

__device__ __forceinline__ void mma16816(float* c, const u32* a, u32 b0, u32 b1) {
    asm volatile(
        "mma.sync.aligned.m16n8k16.row.col.f32.bf16.bf16.f32 "
        "{%0,%1,%2,%3}, {%4,%5,%6,%7}, {%8,%9}, {%0,%1,%2,%3};"
        : "+f"(c[0]), "+f"(c[1]), "+f"(c[2]), "+f"(c[3])
        : "r"(a[0]), "r"(a[1]), "r"(a[2]), "r"(a[3]), "r"(b0), "r"(b1));
}

// ---------------- scratch ----------------------------------------------------
__device__ float g_qkv[NPTS*192];      // q|k|v per point
__device__ int   g_idx[NPTS*KK];       // knn indices
__device__ float g_y[NPTS*DD];         // pre-BN output of fc
__device__ float g_part[ATTN_GRID*2*DD];
__device__ float g_mv[2*DD];           // mean, rstd
__device__ int   g_cellstart[1025];
__device__ float4 g_posb[NPTS];        // cell-sorted (x,y,z,idx)

// ---------------- binning: single-block count+scan+scatter (replay-safe) ----
__device__ __forceinline__ int cell_of(float x, float y, float z, int b) {
    int cx = min(7, max(0, (int)(x * 8.0f)));
    int cy = min(7, max(0, (int)(y * 8.0f)));
    int cz = min(7, max(0, (int)(z * 8.0f)));
    return b*512 + cz*64 + cy*8 + cx;
}

__global__ __launch_bounds__(1024, 1)
void binall_kernel(const float* __restrict__ pos) {
    __shared__ int scnt[1024];
    __shared__ int ssum[1024];
    int tid = threadIdx.x;
    scnt[tid] = 0;
    __syncthreads();
    // count (all state in smem -> graph-replay safe)
#pragma unroll
    for (int k = 0; k < 8; k++) {
        int i = tid + k*1024;
        float x = pos[(size_t)i*3], y = pos[(size_t)i*3+1], z = pos[(size_t)i*3+2];
        atomicAdd(&scnt[cell_of(x, y, z, i >> 12)], 1);
    }
    __syncthreads();
    int c = scnt[tid];
    ssum[tid] = c;
    for (int off = 1; off < 1024; off <<= 1) {
        __syncthreads();
        int v = (tid >= off) ? ssum[tid - off] : 0;
        __syncthreads();
        ssum[tid] += v;
    }
    int excl = ssum[tid] - c;
    g_cellstart[tid] = excl;
    if (tid == 1023) g_cellstart[1024] = ssum[tid];
    __syncthreads();
    scnt[tid] = excl;               // reuse as running cursor
    __syncthreads();
    // scatter
#pragma unroll
    for (int k = 0; k < 8; k++) {
        int i = tid + k*1024;
        float x = pos[(size_t)i*3], y = pos[(size_t)i*3+1], z = pos[(size_t)i*3+2];
        int slot = atomicAdd(&scnt[cell_of(x, y, z, i >> 12)], 1);
        g_posb[slot] = make_float4(x, y, z, __int_as_float(i & 4095));
    }
}

// ---------------- kernel 2: KNN (grid rings + threshold filter, exact) ------
__device__ __forceinline__ bool lexless(float d1, int i1, float d2, int i2) {
    return (d1 < d2) || (d1 == d2 && i1 < i2);
}

__device__ __forceinline__ void knn_flush(
    float& tD, int& tI, float& thrD, int& thrI, float& thr2,
    int& cnt, const float* bD, const int* bI, int lane)
{
    float e0 = (lane < 16) ? tD : BIGD;
    int   q0 = (lane < 16) ? tI : 0x7fffffff;
    float e1 = (lane      < cnt) ? bD[lane]      : BIGD;
    int   q1 = (lane      < cnt) ? bI[lane]      : 0x7fffffff;
    float e2 = (lane + 32 < cnt) ? bD[lane + 32] : BIGD;
    int   q2 = (lane + 32 < cnt) ? bI[lane + 32] : 0x7fffffff;
    float e3 = (lane + 64 < cnt) ? bD[lane + 64] : BIGD;
    int   q3 = (lane + 64 < cnt) ? bI[lane + 64] : 0x7fffffff;
    float e4 = (lane + 96 < cnt) ? bD[lane + 96] : BIGD;
    int   q4 = (lane + 96 < cnt) ? bI[lane + 96] : 0x7fffffff;

    float nD = BIGD; int nI = 0x7fffffff;
#pragma unroll
    for (int r = 0; r < 16; r++) {
        float md = e0; int mi = q0; int ms = 0;
        if (lexless(e1, q1, md, mi)) { md = e1; mi = q1; ms = 1; }
        if (lexless(e2, q2, md, mi)) { md = e2; mi = q2; ms = 2; }
        if (lexless(e3, q3, md, mi)) { md = e3; mi = q3; ms = 3; }
        if (lexless(e4, q4, md, mi)) { md = e4; mi = q4; ms = 4; }
        int src = (lane << 3) | ms;
#pragma unroll
        for (int off = 16; off; off >>= 1) {
            float od = __shfl_xor_sync(0xffffffffu, md, off);
            int   oi = __shfl_xor_sync(0xffffffffu, mi, off);
            int   os = __shfl_xor_sync(0xffffffffu, src, off);
            if (lexless(od, oi, md, mi)) { md = od; mi = oi; src = os; }
        }
        if (lane == (src >> 3)) {
            int sl = src & 7;
            if (sl == 0)      { e0 = BIGD; q0 = 0x7fffffff; }
            else if (sl == 1) { e1 = BIGD; q1 = 0x7fffffff; }
            else if (sl == 2) { e2 = BIGD; q2 = 0x7fffffff; }
            else if (sl == 3) { e3 = BIGD; q3 = 0x7fffffff; }
            else              { e4 = BIGD; q4 = 0x7fffffff; }
        }
        if (lane == r) { nD = md; nI = mi; }
    }
    tD = nD; tI = nI;
    thrD = __shfl_sync(0xffffffffu, nD, 15);
    thrI = __shfl_sync(0xffffffffu, nI, 15);
    thr2 = __fmul_rn(__fmul_rn(thrD, thrD), 1.0000005f);
    cnt = 0;
}

#define KNN_RUN(rowbase, x0v, x1v) do {                                         \
    int s_ = cstart[(rowbase) + (x0v)];                                         \
    int e_ = cstart[(rowbase) + (x1v) + 1];                                     \
    for (int i0 = s_; i0 < e_; i0 += 32) {                                      \
        int j = i0 + lane;                                                      \
        bool push = false; float dv = 0.0f; int ci = 0;                         \
        if (j < e_) {                                                           \
            float4 p = g_posb[j];                                               \
            float dx = px - p.x, dy = py - p.y, dz = pz - p.z;                  \
            float d2 = __fadd_rn(__fadd_rn(__fmul_rn(dx,dx), __fmul_rn(dy,dy)), \
                                 __fmul_rn(dz,dz));                             \
            if (d2 <= thr2) {                                                   \
                dv = sqrtf(d2);                                                 \
                ci = __float_as_int(p.w);                                       \
                push = lexless(dv, ci, thrD, thrI);                             \
            }                                                                   \
        }                                                                       \
        u32 mask = __ballot_sync(0xffffffffu, push);                            \
        if (push) {                                                             \
            int pp = cnt + __popc(mask & ((1u << lane) - 1u));                  \
            bD[pp] = dv; bI[pp] = ci;                                           \
        }                                                                       \
        cnt += __popc(mask);                                                    \
        if (cnt > KNN_CAP - 32)                                                 \
            knn_flush(tD, tI, thrD, thrI, thr2, cnt, bD, bI, lane);             \
    }                                                                           \
} while (0)

__global__ __launch_bounds__(256, 1)
void knn_kernel(const float* __restrict__ pos) {
    __shared__ int cstart[513];
    __shared__ float bufD[8*KNN_CAP];
    __shared__ int   bufI[8*KNN_CAP];
    int tid = threadIdx.x;
    int warp = tid >> 5, lane = tid & 31;
    int q = blockIdx.x * 8 + warp;             // global query id (block = one batch)
    int bq = q >> 12;
    for (int i = tid; i < 513; i += 256) cstart[i] = g_cellstart[bq*512 + i];
    __syncthreads();

    float px = pos[(size_t)q*3 + 0];
    float py = pos[(size_t)q*3 + 1];
    float pz = pos[(size_t)q*3 + 2];
    int cx = min(7, max(0, (int)(px * 8.0f)));
    int cy = min(7, max(0, (int)(py * 8.0f)));
    int cz = min(7, max(0, (int)(pz * 8.0f)));
    float* bD = bufD + warp*KNN_CAP;
    int*   bI = bufI + warp*KNN_CAP;

    float tD = BIGD; int tI = 0x7fff0000 + lane;
    float thrD = BIGD; int thrI = 0x7fffffff;
    float thr2 = __int_as_float(0x7f800000);
    int cnt = 0;

    // ---- phase 1: fused rings 0+1 = 3x3x3 block, uniform full-x rows
    {
        int zlo = max(cz-1, 0), zhi = min(cz+1, 7);
        int ylo = max(cy-1, 0), yhi = min(cy+1, 7);
        int x0 = max(cx-1, 0), x1 = min(cx+1, 7);
        for (int z = zlo; z <= zhi; z++)
            for (int y = ylo; y <= yhi; y++)
                KNN_RUN(z*64 + y*8, x0, x1);
        if (cnt) knn_flush(tD, tI, thrD, thrI, thr2, cnt, bD, bI, lane);
    }

    // ---- phase 2: rings R>=2 until certified
    if (!(thrD < 0.125f * 0.999999f)) {
        for (int R = 2; R < 8; R++) {
            int zlo = max(cz - R, 0), zhi = min(cz + R, 7);
            for (int z = zlo; z <= zhi; z++) {
                int adz = (z > cz) ? (z - cz) : (cz - z);
                int ylo = max(cy - R, 0), yhi = min(cy + R, 7);
                for (int y = ylo; y <= yhi; y++) {
                    int ady = (y > cy) ? (y - cy) : (cy - y);
                    int rowbase = z*64 + y*8;
                    if (adz == R || ady == R) {
                        int x0 = max(cx - R, 0), x1 = min(cx + R, 7);
                        KNN_RUN(rowbase, x0, x1);
                    } else {
                        if (cx - R >= 0) KNN_RUN(rowbase, cx - R, cx - R);
                        if (cx + R <= 7) KNN_RUN(rowbase, cx + R, cx + R);
                    }
                }
            }
            if (cnt) knn_flush(tD, tI, thrD, thrI, thr2, cnt, bD, bI, lane);
            if (thrD < (float)R * 0.125f * 0.999999f) break;
        }
    }

    if (lane < 16) g_idx[q*KK + lane] = tI;
}

// ---------------- kernel 1: QKV GEMM  (8192x64 @ 64x192) -------------------
__global__ void qkv_kernel(const float* __restrict__ x,
                           const float* __restrict__ w,
                           const float* __restrict__ bq) {
    extern __shared__ float sm[];
    float* ws = sm;             // 64*192
    float* xs = sm + 64*192;    // 64*64
    int tid = threadIdx.x;      // 192 threads
    for (int i = tid; i < 64*192; i += 192) ws[i] = w[i];
    int row0 = blockIdx.x * 64;
    for (int i = tid; i < 64*64; i += 192) xs[i] = x[row0*64 + i];
    __syncthreads();
    float bb = bq[tid];
    for (int r0 = 0; r0 < 64; r0 += 8) {
        float acc[8];
#pragma unroll
        for (int r = 0; r < 8; r++) acc[r] = bb;
        for (int i = 0; i < 64; i++) {
            float wv = ws[i*192 + tid];
#pragma unroll
            for (int r = 0; r < 8; r++) acc[r] = fmaf(xs[(r0+r)*64 + i], wv, acc[r]);
        }
#pragma unroll
        for (int r = 0; r < 8; r++) g_qkv[(row0 + r0 + r)*192 + tid] = acc[r];
    }
}

// ---------------- kernel 3: fused attn (all GEMMs on tensor cores) ----------
__global__ __launch_bounds__(512, 1)
void attn_kernel(const float* __restrict__ pos,
                 const float* __restrict__ w_p1, const float* __restrict__ b_p1,
                 const float* __restrict__ w_p2, const float* __restrict__ b_p2,
                 const float* __restrict__ w_a1, const float* __restrict__ b_a1,
                 const float* __restrict__ w_a2, const float* __restrict__ b_a2,
                 const float* __restrict__ w_fc, const float* __restrict__ b_fc) {
    extern __shared__ float sm[];
    u32* w1hi  = (u32*)sm;                // 8192
    u32* w1lo  = w1hi + 8192;             // 8192
    u32* w2hi  = w1lo + 8192;             // 8192
    u32* w2lo  = w2hi + 8192;             // 8192
    u32* w2phi = w2lo + 8192;             // 2048  (w_p2 as MMA-B)
    u32* w2plo = w2phi + 2048;            // 2048
    u32* t1hi  = w2plo + 2048;            // 4608  [row x 36]  (alias: stage)
    u32* t1lo  = t1hi + 4608;             // 4608
    u32* h2hi  = t1lo + 4608;             // 4608  [row x 36]  (alias: scores)
    u32* h2lo  = h2hi + 4608;             // 4608
    float* qs    = (float*)(h2lo + 4608); // 512
    float* p0s   = qs + 512;              // 32
    float* rel   = p0s + 32;              // 384
    float* aggs  = rel + 384;             // 512
    float* b_p1s = aggs + 512;            // 64
    float* b_p2s = b_p1s + 64;            // 64
    float* b_a1s = b_p2s + 64;            // 256
    float* b_a2s = b_a1s + 256;           // 64
    float* b_fcs = b_a2s + 64;            // 64
    float* w_p1s = b_fcs + 64;            // 192
    int*   sidx  = (int*)(w_p1s + 192);   // 128
    float* stage  = (float*)t1hi;         // 8 x 1056 = 8448 f32 (<= 9216 u32)
    float* scores = (float*)h2hi;         // 128 x 65 = 8320 f32 (<= 9216 u32)

    int tid = threadIdx.x;
    int lane = tid & 31;
    int wid = tid >> 5;
    int g4 = lane >> 2, t4 = lane & 3;
    int mt = wid >> 1, hf = wid & 1;      // MLP-chain mapping
    int mtp = wid >> 1, nh = wid & 1;     // p2-MMA mapping (same split)

    // ---- weight prep: bf16 split + fragment swizzle (once) ----
    for (int i = tid; i < 8192; i += 512) {
        int kp = i >> 8, n = i & 255;
        u32 hi, lo;
        split2(w_a1[(2*kp)*256 + n], w_a1[(2*kp+1)*256 + n], hi, lo);
        int dst = kp*256 + (n ^ ((kp & 3) << 3));
        w1hi[dst] = hi; w1lo[dst] = lo;
    }
    for (int i = tid; i < 8192; i += 512) {
        int kp = i >> 6, n = i & 63;
        u32 hi, lo;
        split2(w_a2[(2*kp)*64 + n], w_a2[(2*kp+1)*64 + n], hi, lo);
        int dst = kp*64 + (n ^ ((kp & 3) << 3));
        w2hi[dst] = hi; w2lo[dst] = lo;
    }
    for (int i = tid; i < 2048; i += 512) {
        int kp = i >> 6, n = i & 63;
        u32 hi, lo;
        split2(w_p2[(2*kp)*64 + n], w_p2[(2*kp+1)*64 + n], hi, lo);
        int dst = kp*64 + (n ^ ((kp & 3) << 3));
        w2phi[dst] = hi; w2plo[dst] = lo;
    }
    if (tid < 192) w_p1s[tid] = w_p1[tid];
    if (tid < 256) b_a1s[tid] = b_a1[tid];
    if (tid < 64) {
        b_p1s[tid] = b_p1[tid]; b_p2s[tid] = b_p2[tid];
        b_a2s[tid] = b_a2[tid]; b_fcs[tid] = b_fc[tid];
    }
    float accY = 0.0f, accY2 = 0.0f;
    __syncthreads();

    for (int g = blockIdx.x; g < NPTS/PTS; g += ATTN_GRID) {
        int pbase = g * PTS;
        int bofs = (pbase >> 12) << 12;

        // ---- A: per-point loads
        if (tid < 128) sidx[tid] = g_idx[pbase*KK + tid];
        {
            int l = tid >> 6, d = tid & 63;
            qs[tid] = g_qkv[(size_t)(pbase + l)*192 + d];
        }
        if (tid < 24) {
            int l = tid / 3, c = tid - l*3;
            p0s[l*4 + c] = pos[(size_t)(pbase + l)*3 + c];
        }
        __syncthreads();

        // ---- B: rel
        if (tid < 384) {
            int r = tid / 3, c = tid - r*3;
            int l = r >> 4;
            rel[tid] = p0s[l*4 + c] - pos[(size_t)(bofs + sidx[r])*3 + c];
        }
        __syncthreads();

        // ---- C: pos-MLP -> t1 (bf16 split tiles)
#pragma unroll
        for (int e = 0; e < 8; e++) {
            int i = tid + e*512;              // 4096 pairs
            int r = i >> 5, kp = i & 31;
            int pp = kp*2;
            float r0v = rel[r*3+0], r1v = rel[r*3+1], r2v = rel[r*3+2];
            float a0 = b_p1s[pp];
            a0 = fmaf(r0v, w_p1s[pp],        a0);
            a0 = fmaf(r1v, w_p1s[64 + pp],   a0);
            a0 = fmaf(r2v, w_p1s[128 + pp],  a0);
            float a1 = b_p1s[pp+1];
            a1 = fmaf(r0v, w_p1s[pp+1],      a1);
            a1 = fmaf(r1v, w_p1s[64 + pp+1], a1);
            a1 = fmaf(r2v, w_p1s[128 + pp+1],a1);
            a0 = fmaxf(a0, 0.0f); a1 = fmaxf(a1, 0.0f);
            u32 hi, lo;
            split2(a0, a1, hi, lo);
            t1hi[r*H2P + kp] = hi;
            t1lo[r*H2P + kp] = lo;
        }
        __syncthreads();

        // ---- D: p2 on MMA (hi/lo chains split for ILP) + qk gather -> h2
        {
            u32 pahi[16], palo[16];
            int rowA = mtp*16 + g4;
#pragma unroll
            for (int ks = 0; ks < 4; ks++) {
                int c = ks*8 + t4;
                pahi[ks*4+0] = t1hi[rowA*H2P + c];
                pahi[ks*4+1] = t1hi[(rowA+8)*H2P + c];
                pahi[ks*4+2] = t1hi[rowA*H2P + c + 4];
                pahi[ks*4+3] = t1hi[(rowA+8)*H2P + c + 4];
                palo[ks*4+0] = t1lo[rowA*H2P + c];
                palo[ks*4+1] = t1lo[(rowA+8)*H2P + c];
                palo[ks*4+2] = t1lo[rowA*H2P + c + 4];
                palo[ks*4+3] = t1lo[(rowA+8)*H2P + c + 4];
            }
            float cP[16], cQ[16];
#pragma unroll
            for (int z = 0; z < 16; z++) { cP[z] = 0.0f; cQ[z] = 0.0f; }
#pragma unroll
            for (int ntl = 0; ntl < 4; ntl++) {
                int nsw = (nh*32 + ntl*8 + g4) ^ (t4 << 3);
#pragma unroll
                for (int ks = 0; ks < 4; ks++) {
                    int kp0 = ks*8 + t4;
                    u32 bh0 = w2phi[kp0*64 + nsw];
                    u32 bh1 = w2phi[(kp0+4)*64 + nsw];
                    u32 bl0 = w2plo[kp0*64 + nsw];
                    u32 bl1 = w2plo[(kp0+4)*64 + nsw];
                    mma16816(&cP[ntl*4], &pahi[ks*4], bh0, bh1);   // hh chain
                    mma16816(&cQ[ntl*4], &pahi[ks*4], bl0, bl1);   // hl+lh chain
                    mma16816(&cQ[ntl*4], &palo[ks*4], bh0, bh1);
                }
            }
            int r1 = mtp*16 + g4, r2 = r1 + 8;
            const float* krow1 = g_qkv + (size_t)(bofs + sidx[r1])*192 + 64;
            const float* krow2 = g_qkv + (size_t)(bofs + sidx[r2])*192 + 64;
#pragma unroll
            for (int ntl = 0; ntl < 4; ntl++) {
                int cb = nh*32 + ntl*8 + t4*2;
                float2 k1 = *(const float2*)&krow1[cb];
                float2 k2 = *(const float2*)&krow2[cb];
                float2 q1 = *(const float2*)&qs[mtp*64 + cb];
                float bb0 = b_p2s[cb], bb1 = b_p2s[cb+1];
                float h10 = (q1.x - k1.x) + (cP[ntl*4+0] + cQ[ntl*4+0]) + bb0;
                float h11 = (q1.y - k1.y) + (cP[ntl*4+1] + cQ[ntl*4+1]) + bb1;
                float h20 = (q1.x - k2.x) + (cP[ntl*4+2] + cQ[ntl*4+2]) + bb0;
                float h21 = (q1.y - k2.y) + (cP[ntl*4+3] + cQ[ntl*4+3]) + bb1;
                int kp = cb >> 1;
                u32 hi, lo;
                split2(h10, h11, hi, lo);
                h2hi[r1*H2P + kp] = hi; h2lo[r1*H2P + kp] = lo;
                split2(h20, h21, hi, lo);
                h2hi[r2*H2P + kp] = hi; h2lo[r2*H2P + kp] = lo;
            }
        }
        __syncthreads();

        // ---- E: load A1 fragments (h2) for this warp's m-tile
        u32 ahi[16], alo[16];
        {
            int rowA = mt*16 + g4;
#pragma unroll
            for (int ks = 0; ks < 4; ks++) {
                int c = ks*8 + t4;
                ahi[ks*4+0] = h2hi[rowA*H2P + c];
                ahi[ks*4+1] = h2hi[(rowA+8)*H2P + c];
                ahi[ks*4+2] = h2hi[rowA*H2P + c + 4];
                ahi[ks*4+3] = h2hi[(rowA+8)*H2P + c + 4];
                alo[ks*4+0] = h2lo[rowA*H2P + c];
                alo[ks*4+1] = h2lo[(rowA+8)*H2P + c];
                alo[ks*4+2] = h2lo[rowA*H2P + c + 4];
                alo[ks*4+3] = h2lo[(rowA+8)*H2P + c + 4];
            }
        }

        // ---- F: chunked attn MLP on tensor cores (sync-free)
        float C2[32];
#pragma unroll
        for (int z = 0; z < 32; z++) C2[z] = 0.0f;

#pragma unroll
        for (int jc = 0; jc < 4; jc++) {
            u32 s2hi[8], s2lo[8];
#pragma unroll
            for (int u = 0; u < 2; u++) {
                // hh chains (cA/cB) and hl+lh chains (cAq/cBq): 4 indep chains
                float cA[4] = {0,0,0,0}, cB[4] = {0,0,0,0};
                float cAq[4] = {0,0,0,0}, cBq[4] = {0,0,0,0};
                int nbase = jc*64 + hf*32 + u*16;
                int nswA = (nbase + g4) ^ (t4 << 3);
                int nswB = (nbase + 8 + g4) ^ (t4 << 3);
#pragma unroll
                for (int ks = 0; ks < 4; ks++) {
                    int kp0 = ks*8 + t4;
                    u32 bh0 = w1hi[kp0*256 + nswA];
                    u32 bh1 = w1hi[(kp0+4)*256 + nswA];
                    u32 bl0 = w1lo[kp0*256 + nswA];
                    u32 bl1 = w1lo[(kp0+4)*256 + nswA];
                    mma16816(cA,  &ahi[ks*4], bh0, bh1);
                    mma16816(cAq, &ahi[ks*4], bl0, bl1);
                    mma16816(cAq, &alo[ks*4], bh0, bh1);
                    u32 ch0 = w1hi[kp0*256 + nswB];
                    u32 ch1 = w1hi[(kp0+4)*256 + nswB];
                    u32 cl0 = w1lo[kp0*256 + nswB];
                    u32 cl1 = w1lo[(kp0+4)*256 + nswB];
                    mma16816(cB,  &ahi[ks*4], ch0, ch1);
                    mma16816(cBq, &ahi[ks*4], cl0, cl1);
                    mma16816(cBq, &alo[ks*4], ch0, ch1);
                }
                int cb = nbase + t4*2;
                float bA0 = b_a1s[cb],   bA1 = b_a1s[cb+1];
                float bB0 = b_a1s[cb+8], bB1 = b_a1s[cb+9];
                float sA0 = fmaxf((cA[0] + cAq[0]) + bA0, 0.0f);
                float sA1 = fmaxf((cA[1] + cAq[1]) + bA1, 0.0f);
                float sA2 = fmaxf((cA[2] + cAq[2]) + bA0, 0.0f);
                float sA3 = fmaxf((cA[3] + cAq[3]) + bA1, 0.0f);
                float sB0 = fmaxf((cB[0] + cBq[0]) + bB0, 0.0f);
                float sB1 = fmaxf((cB[1] + cBq[1]) + bB1, 0.0f);
                float sB2 = fmaxf((cB[2] + cBq[2]) + bB0, 0.0f);
                float sB3 = fmaxf((cB[3] + cBq[3]) + bB1, 0.0f);
                split2(sA0, sA1, s2hi[u*4+0], s2lo[u*4+0]);
                split2(sA2, sA3, s2hi[u*4+1], s2lo[u*4+1]);
                split2(sB0, sB1, s2hi[u*4+2], s2lo[u*4+2]);
                split2(sB2, sB3, s2hi[u*4+3], s2lo[u*4+3]);
            }
#pragma unroll
            for (int nt = 0; nt < 8; nt++) {
#pragma unroll
                for (int u = 0; u < 2; u++) {
                    int kp = jc*32 + hf*16 + u*8 + t4;
                    int nsw = (nt*8 + g4) ^ (t4 << 3);
                    u32 bh0 = w2hi[kp*64 + nsw];
                    u32 bh1 = w2hi[(kp+4)*64 + nsw];
                    u32 bl0 = w2lo[kp*64 + nsw];
                    u32 bl1 = w2lo[(kp+4)*64 + nsw];
                    mma16816(&C2[nt*4], &s2hi[u*4], bh0, bh1);
                    mma16816(&C2[nt*4], &s2hi[u*4], bl0, bl1);
                    mma16816(&C2[nt*4], &s2lo[u*4], bh0, bh1);
                }
            }
        }

        // ---- cross-half reduction of scores (stage in t1 region)
        if (hf) {
            float* sp = stage + mt*1056 + lane*33;
#pragma unroll
            for (int z = 0; z < 32; z++) sp[z] = C2[z];
        }
        __syncthreads();
        if (!hf) {
            float* sp = stage + mt*1056 + lane*33;
#pragma unroll
            for (int nt = 0; nt < 8; nt++) {
                int cb = nt*8 + t4*2;
                float v0 = C2[nt*4+0] + sp[nt*4+0] + b_a2s[cb];
                float v1 = C2[nt*4+1] + sp[nt*4+1] + b_a2s[cb+1];
                float v2 = C2[nt*4+2] + sp[nt*4+2] + b_a2s[cb];
                float v3 = C2[nt*4+3] + sp[nt*4+3] + b_a2s[cb+1];
                scores[(mt*16 + g4)*SCP + cb]         = v0;
                scores[(mt*16 + g4)*SCP + cb + 1]     = v1;
                scores[(mt*16 + g4 + 8)*SCP + cb]     = v2;
                scores[(mt*16 + g4 + 8)*SCP + cb + 1] = v3;
            }
        }
        __syncthreads();

        // ---- G: softmax over K + weighted v-sum (v from L2)
        {
            int l = tid >> 6, d = tid & 63;
            float vreg[16];
#pragma unroll
            for (int k = 0; k < 16; k++)
                vreg[k] = g_qkv[(size_t)(bofs + sidx[l*16 + k])*192 + 128 + d];
            float mx = -3.0e38f;
#pragma unroll
            for (int k = 0; k < 16; k++)
                mx = fmaxf(mx, scores[(l*16 + k)*SCP + d]);
            float ssum = 0.0f, a = 0.0f;
#pragma unroll
            for (int k = 0; k < 16; k++) {
                float e = __expf(scores[(l*16 + k)*SCP + d] - mx);
                ssum += e;
                a = fmaf(e, vreg[k], a);
            }
            aggs[tid] = a / ssum;
        }
        __syncthreads();

        // ---- H: fc (w_fc via L1/L2) + BN partials
        {
            int l = tid >> 6, d = tid & 63;
            float y = b_fcs[d];
#pragma unroll 8
            for (int c = 0; c < 64; c++)
                y = fmaf(aggs[l*64 + c], w_fc[c*64 + d], y);
            g_y[(size_t)(pbase + l)*64 + d] = y;
            accY += y;
            accY2 = fmaf(y, y, accY2);
        }
        __syncthreads();
    }

    // ---- reduce BN partials (t1 region as scratch)
    float* red = (float*)t1hi;
    red[tid] = accY;
    __syncthreads();
    if (tid < 64) {
        float s = 0.0f;
#pragma unroll
        for (int q = 0; q < 8; q++) s += red[q*64 + tid];
        g_part[blockIdx.x*128 + tid] = s;
    }
    __syncthreads();
    red[tid] = accY2;
    __syncthreads();
    if (tid < 64) {
        float s = 0.0f;
#pragma unroll
        for (int q = 0; q < 8; q++) s += red[q*64 + tid];
        g_part[blockIdx.x*128 + 64 + tid] = s;
    }
}

// ---------------- kernel 4: finish BN statistics ----------------------------
__global__ void bnstats_kernel() {
    __shared__ float sred[2048];
    int tid = threadIdx.x;            // 1024
    int d = tid & 63, q = tid >> 6;   // 16 groups
    float s = 0.0f, s2 = 0.0f;
    for (int blk = q; blk < ATTN_GRID; blk += 16) {
        s  += g_part[blk*128 + d];
        s2 += g_part[blk*128 + 64 + d];
    }
    sred[tid] = s; sred[1024 + tid] = s2;
    __syncthreads();
    if (tid < 64) {
        float ts = 0.0f, ts2 = 0.0f;
#pragma unroll
        for (int k = 0; k < 16; k++) {
            ts  += sred[k*64 + d];
            ts2 += sred[1024 + k*64 + d];
        }
        float mean = ts / (float)NPTS;
        float var  = ts2 / (float)NPTS - mean*mean;
        g_mv[d]      = mean;
        g_mv[64 + d] = rsqrtf(var + 1e-5f);
    }
}

// ---------------- kernel 5: BN apply + relu + residual ----------------------
__global__ void final_kernel(const float* __restrict__ x,
                             const float* __restrict__ gamma,
                             const float* __restrict__ beta,
                             float* __restrict__ out) {
    int i = blockIdx.x * blockDim.x + threadIdx.x;
    if (i < NPTS*DD) {
        int d = i & 63;
        float yv = (g_y[i] - g_mv[d]) * g_mv[64 + d] * gamma[d] + beta[d];
        out[i] = fmaxf(yv, 0.0f) + x[i];
    }
}

// ---------------- launch -----------------------------------------------------
extern "C" void kernel_launch(void* const* d_in, const int* in_sizes, int n_in,
                              void* d_out, int out_size) {
    const float* x     = (const float*)d_in[0];
    const float* pos   = (const float*)d_in[1];
    const float* w_qkv = (const float*)d_in[2];
    const float* b_qkv = (const float*)d_in[3];
    const float* w_p1  = (const float*)d_in[4];
    const float* b_p1  = (const float*)d_in[5];
    const float* w_p2  = (const float*)d_in[6];
    const float* b_p2  = (const float*)d_in[7];
    const float* w_a1  = (const float*)d_in[8];
    const float* b_a1  = (const float*)d_in[9];
    const float* w_a2  = (const float*)d_in[10];
    const float* b_a2  = (const float*)d_in[11];
    const float* w_fc  = (const float*)d_in[12];
    const float* b_fc  = (const float*)d_in[13];
    const float* gamma = (const float*)d_in[14];
    const float* beta  = (const float*)d_in[15];
    float* out = (float*)d_out;

    const int smem_qkv  = (64*192 + 64*64) * 4;
    const int smem_attn = (8192*4 + 2048*2 + 4608*4
                           + 512 + 32 + 384 + 512
                           + 64 + 64 + 256 + 64 + 64 + 192 + 128) * 4;  // 230272 B

    cudaFuncSetAttribute(qkv_kernel,  cudaFuncAttributeMaxDynamicSharedMemorySize, smem_qkv);
    cudaFuncSetAttribute(attn_kernel, cudaFuncAttributeMaxDynamicSharedMemorySize, smem_attn);

    binall_kernel<<<1, 1024>>>(pos);                    // 0
    knn_kernel<<<NPTS/8, 256>>>(pos);                   // 1
    qkv_kernel<<<NPTS/64, 192, smem_qkv>>>(x, w_qkv, b_qkv);   // 2
    attn_kernel<<<ATTN_GRID, 512, smem_attn>>>(pos, w_p1, b_p1, w_p2, b_p2,
                                               w_a1, b_a1, w_a2, b_a2,
                                               w_fc, b_fc);    // 3 <- capture slot
    bnstats_kernel<<<1, 1024>>>();
    final_kernel<<<(NPTS*DD + 255)/256, 256>>>(x, gamma, beta, out);
}

// round 15
// speedup vs baseline: 1.0394x; 1.0394x over previous
#include <cuda_runtime.h>
#include <cuda_bf16.h>
#include <math.h>

#define BB 2
#define NN 4096
#define DD 64
#define HH 256
#define KK 16
#define NPTS (BB*NN)
#define ATTN_GRID 148
#define PTS 8               // points per iteration
#define ROWS 128            // PTS * KK rows
#define H2P 36              // packed bf16x2 row stride (u32)
#define SCP 65              // scores row stride

#define KNN_CAP 128
#define BIGD 3.0e38f

typedef unsigned long long u64;
typedef unsigned int u32;

// split two fp32 into packed bf16x2 hi and lo parts (x0 -> low half).
// Fast path: packed cvt.rn.bf16x2.f32 (identical rounding to scalar rn).
__device__ __forceinline__ void split2(float x0, float x1, u32& hi, u32& lo) {
    u32 h;
    asm("cvt.rn.bf16x2.f32 %0, %1, %2;" : "=r"(h) : "f"(x1), "f"(x0));
    float h0 = __uint_as_float(h << 16);
    float h1 = __uint_as_float(h & 0xffff0000u);
    u32 l;
    asm("cvt.rn.bf16x2.f32 %0, %1, %2;" : "=r"(l) : "f"(x1 - h1), "f"(x0 - h0));
    hi = h; lo = l;
}

__device__ __forceinline__ void mma16816(float* c, const u32* a, u32 b0, u32 b1) {
    asm volatile(
        "mma.sync.aligned.m16n8k16.row.col.f32.bf16.bf16.f32 "
        "{%0,%1,%2,%3}, {%4,%5,%6,%7}, {%8,%9}, {%0,%1,%2,%3};"
        : "+f"(c[0]), "+f"(c[1]), "+f"(c[2]), "+f"(c[3])
        : "r"(a[0]), "r"(a[1]), "r"(a[2]), "r"(a[3]), "r"(b0), "r"(b1));
}

// ---------------- scratch ----------------------------------------------------
__device__ float g_qkv[NPTS*192];      // q|k|v per point
__device__ int   g_idx[NPTS*KK];       // knn indices
__device__ float g_y[NPTS*DD];         // pre-BN output of fc
__device__ float g_part[ATTN_GRID*2*DD];
__device__ float g_mv[2*DD];           // mean, rstd
__device__ int   g_cellcnt[1024];      // zero-init at load; re-zeroed by scatter
__device__ int   g_cellstart[1025];
__device__ int   g_cellcur[1024];
__device__ float4 g_posb[NPTS];        // cell-sorted (x,y,z,idx)

// ---------------- binning kernels (3-kernel parallel version) ----------------
__device__ __forceinline__ int cell_of(float x, float y, float z, int b) {
    int cx = min(7, max(0, (int)(x * 8.0f)));
    int cy = min(7, max(0, (int)(y * 8.0f)));
    int cz = min(7, max(0, (int)(z * 8.0f)));
    return b*512 + cz*64 + cy*8 + cx;
}

__global__ void bincount_kernel(const float* __restrict__ pos) {
    int i = blockIdx.x*blockDim.x + threadIdx.x;
    if (i < NPTS) {
        float x = pos[(size_t)i*3], y = pos[(size_t)i*3+1], z = pos[(size_t)i*3+2];
        atomicAdd(&g_cellcnt[cell_of(x, y, z, i >> 12)], 1);
    }
}

__global__ void binprefix_kernel() {
    __shared__ int sh[1024];
    int tid = threadIdx.x;
    int c = g_cellcnt[tid];
    sh[tid] = c;
    for (int off = 1; off < 1024; off <<= 1) {
        __syncthreads();
        int v = (tid >= off) ? sh[tid - off] : 0;
        __syncthreads();
        sh[tid] += v;
    }
    int excl = sh[tid] - c;
    g_cellstart[tid] = excl;
    g_cellcur[tid] = excl;
    if (tid == 1023) g_cellstart[1024] = sh[tid];
}

__global__ void binscatter_kernel(const float* __restrict__ pos) {
    int i = blockIdx.x*blockDim.x + threadIdx.x;
    if (i < 1024) g_cellcnt[i] = 0;          // reset for next launch/replay
    if (i < NPTS) {
        float x = pos[(size_t)i*3], y = pos[(size_t)i*3+1], z = pos[(size_t)i*3+2];
        int slot = atomicAdd(&g_cellcur[cell_of(x, y, z, i >> 12)], 1);
        g_posb[slot] = make_float4(x, y, z, __int_as_float(i & 4095));
    }
}

// ---------------- kernel 2: KNN (grid rings + threshold filter, exact) ------
__device__ __forceinline__ bool lexless(float d1, int i1, float d2, int i2) {
    return (d1 < d2) || (d1 == d2 && i1 < i2);
}

__device__ __forceinline__ void knn_flush(
    float& tD, int& tI, float& thrD, int& thrI, float& thr2,
    int& cnt, const float* bD, const int* bI, int lane)
{
    float e0 = (lane < 16) ? tD : BIGD;
    int   q0 = (lane < 16) ? tI : 0x7fffffff;
    float e1 = (lane      < cnt) ? bD[lane]      : BIGD;
    int   q1 = (lane      < cnt) ? bI[lane]      : 0x7fffffff;
    float e2 = (lane + 32 < cnt) ? bD[lane + 32] : BIGD;
    int   q2 = (lane + 32 < cnt) ? bI[lane + 32] : 0x7fffffff;
    float e3 = (lane + 64 < cnt) ? bD[lane + 64] : BIGD;
    int   q3 = (lane + 64 < cnt) ? bI[lane + 64] : 0x7fffffff;
    float e4 = (lane + 96 < cnt) ? bD[lane + 96] : BIGD;
    int   q4 = (lane + 96 < cnt) ? bI[lane + 96] : 0x7fffffff;

    float nD = BIGD; int nI = 0x7fffffff;
#pragma unroll
    for (int r = 0; r < 16; r++) {
        float md = e0; int mi = q0; int ms = 0;
        if (lexless(e1, q1, md, mi)) { md = e1; mi = q1; ms = 1; }
        if (lexless(e2, q2, md, mi)) { md = e2; mi = q2; ms = 2; }
        if (lexless(e3, q3, md, mi)) { md = e3; mi = q3; ms = 3; }
        if (lexless(e4, q4, md, mi)) { md = e4; mi = q4; ms = 4; }
        int src = (lane << 3) | ms;
#pragma unroll
        for (int off = 16; off; off >>= 1) {
            float od = __shfl_xor_sync(0xffffffffu, md, off);
            int   oi = __shfl_xor_sync(0xffffffffu, mi, off);
            int   os = __shfl_xor_sync(0xffffffffu, src, off);
            if (lexless(od, oi, md, mi)) { md = od; mi = oi; src = os; }
        }
        if (lane == (src >> 3)) {
            int sl = src & 7;
            if (sl == 0)      { e0 = BIGD; q0 = 0x7fffffff; }
            else if (sl == 1) { e1 = BIGD; q1 = 0x7fffffff; }
            else if (sl == 2) { e2 = BIGD; q2 = 0x7fffffff; }
            else if (sl == 3) { e3 = BIGD; q3 = 0x7fffffff; }
            else              { e4 = BIGD; q4 = 0x7fffffff; }
        }
        if (lane == r) { nD = md; nI = mi; }
    }
    tD = nD; tI = nI;
    thrD = __shfl_sync(0xffffffffu, nD, 15);
    thrI = __shfl_sync(0xffffffffu, nI, 15);
    thr2 = __fmul_rn(__fmul_rn(thrD, thrD), 1.0000005f);
    cnt = 0;
}

#define KNN_RUN(rowbase, x0v, x1v) do {                                         \
    int s_ = cstart[(rowbase) + (x0v)];                                         \
    int e_ = cstart[(rowbase) + (x1v) + 1];                                     \
    for (int i0 = s_; i0 < e_; i0 += 32) {                                      \
        int j = i0 + lane;                                                      \
        bool push = false; float dv = 0.0f; int ci = 0;                         \
        if (j < e_) {                                                           \
            float4 p = g_posb[j];                                               \
            float dx = px - p.x, dy = py - p.y, dz = pz - p.z;                  \
            float d2 = __fadd_rn(__fadd_rn(__fmul_rn(dx,dx), __fmul_rn(dy,dy)), \
                                 __fmul_rn(dz,dz));                             \
            if (d2 <= thr2) {                                                   \
                dv = sqrtf(d2);                                                 \
                ci = __float_as_int(p.w);                                       \
                push = lexless(dv, ci, thrD, thrI);                             \
            }                                                                   \
        }                                                                       \
        u32 mask = __ballot_sync(0xffffffffu, push);                            \
        if (push) {                                                             \
            int pp = cnt + __popc(mask & ((1u << lane) - 1u));                  \
            bD[pp] = dv; bI[pp] = ci;                                           \
        }                                                                       \
        cnt += __popc(mask);                                                    \
        if (cnt > KNN_CAP - 32)                                                 \
            knn_flush(tD, tI, thrD, thrI, thr2, cnt, bD, bI, lane);             \
    }                                                                           \
} while (0)

__global__ __launch_bounds__(256, 1)
void knn_kernel(const float* __restrict__ pos) {
    __shared__ int cstart[513];
    __shared__ float bufD[8*KNN_CAP];
    __shared__ int   bufI[8*KNN_CAP];
    int tid = threadIdx.x;
    int warp = tid >> 5, lane = tid & 31;
    int q = blockIdx.x * 8 + warp;             // global query id (block = one batch)
    int bq = q >> 12;
    for (int i = tid; i < 513; i += 256) cstart[i] = g_cellstart[bq*512 + i];
    __syncthreads();

    float px = pos[(size_t)q*3 + 0];
    float py = pos[(size_t)q*3 + 1];
    float pz = pos[(size_t)q*3 + 2];
    int cx = min(7, max(0, (int)(px * 8.0f)));
    int cy = min(7, max(0, (int)(py * 8.0f)));
    int cz = min(7, max(0, (int)(pz * 8.0f)));
    float* bD = bufD + warp*KNN_CAP;
    int*   bI = bufI + warp*KNN_CAP;

    float tD = BIGD; int tI = 0x7fff0000 + lane;
    float thrD = BIGD; int thrI = 0x7fffffff;
    float thr2 = __int_as_float(0x7f800000);
    int cnt = 0;

    // ---- phase 1: fused rings 0+1 = 3x3x3 block, uniform full-x rows
    {
        int zlo = max(cz-1, 0), zhi = min(cz+1, 7);
        int ylo = max(cy-1, 0), yhi = min(cy+1, 7);
        int x0 = max(cx-1, 0), x1 = min(cx+1, 7);
        for (int z = zlo; z <= zhi; z++)
            for (int y = ylo; y <= yhi; y++)
                KNN_RUN(z*64 + y*8, x0, x1);
        if (cnt) knn_flush(tD, tI, thrD, thrI, thr2, cnt, bD, bI, lane);
    }

    // ---- phase 2: rings R>=2 until certified
    if (!(thrD < 0.125f * 0.999999f)) {
        for (int R = 2; R < 8; R++) {
            int zlo = max(cz - R, 0), zhi = min(cz + R, 7);
            for (int z = zlo; z <= zhi; z++) {
                int adz = (z > cz) ? (z - cz) : (cz - z);
                int ylo = max(cy - R, 0), yhi = min(cy + R, 7);
                for (int y = ylo; y <= yhi; y++) {
                    int ady = (y > cy) ? (y - cy) : (cy - y);
                    int rowbase = z*64 + y*8;
                    if (adz == R || ady == R) {
                        int x0 = max(cx - R, 0), x1 = min(cx + R, 7);
                        KNN_RUN(rowbase, x0, x1);
                    } else {
                        if (cx - R >= 0) KNN_RUN(rowbase, cx - R, cx - R);
                        if (cx + R <= 7) KNN_RUN(rowbase, cx + R, cx + R);
                    }
                }
            }
            if (cnt) knn_flush(tD, tI, thrD, thrI, thr2, cnt, bD, bI, lane);
            if (thrD < (float)R * 0.125f * 0.999999f) break;
        }
    }

    if (lane < 16) g_idx[q*KK + lane] = tI;
}

// ---------------- kernel 1: QKV GEMM  (8192x64 @ 64x192) -------------------
__global__ void qkv_kernel(const float* __restrict__ x,
                           const float* __restrict__ w,
                           const float* __restrict__ bq) {
    extern __shared__ float sm[];
    float* ws = sm;             // 64*192
    float* xs = sm + 64*192;    // 64*64
    int tid = threadIdx.x;      // 192 threads
    for (int i = tid; i < 64*192; i += 192) ws[i] = w[i];
    int row0 = blockIdx.x * 64;
    for (int i = tid; i < 64*64; i += 192) xs[i] = x[row0*64 + i];
    __syncthreads();
    float bb = bq[tid];
    for (int r0 = 0; r0 < 64; r0 += 8) {
        float acc[8];
#pragma unroll
        for (int r = 0; r < 8; r++) acc[r] = bb;
        for (int i = 0; i < 64; i++) {
            float wv = ws[i*192 + tid];
#pragma unroll
            for (int r = 0; r < 8; r++) acc[r] = fmaf(xs[(r0+r)*64 + i], wv, acc[r]);
        }
#pragma unroll
        for (int r = 0; r < 8; r++) g_qkv[(row0 + r0 + r)*192 + tid] = acc[r];
    }
}

// ---------------- kernel 3: fused attn (all GEMMs on tensor cores) ----------
__global__ __launch_bounds__(512, 1)
void attn_kernel(const float* __restrict__ pos,
                 const float* __restrict__ w_p1, const float* __restrict__ b_p1,
                 const float* __restrict__ w_p2, const float* __restrict__ b_p2,
                 const float* __restrict__ w_a1, const float* __restrict__ b_a1,
                 const float* __restrict__ w_a2, const float* __restrict__ b_a2,
                 const float* __restrict__ w_fc, const float* __restrict__ b_fc) {
    extern __shared__ float sm[];
    u32* w1hi  = (u32*)sm;                // 8192
    u32* w1lo  = w1hi + 8192;             // 8192
    u32* w2hi  = w1lo + 8192;             // 8192
    u32* w2lo  = w2hi + 8192;             // 8192
    u32* w2phi = w2lo + 8192;             // 2048  (w_p2 as MMA-B)
    u32* w2plo = w2phi + 2048;            // 2048
    u32* t1hi  = w2plo + 2048;            // 4608  [row x 36]  (alias: stage)
    u32* t1lo  = t1hi + 4608;             // 4608
    u32* h2hi  = t1lo + 4608;             // 4608  [row x 36]  (alias: scores)
    u32* h2lo  = h2hi + 4608;             // 4608
    float* qs    = (float*)(h2lo + 4608); // 512
    float* p0s   = qs + 512;              // 32
    float* rel   = p0s + 32;              // 384
    float* aggs  = rel + 384;             // 512
    float* b_p1s = aggs + 512;            // 64
    float* b_p2s = b_p1s + 64;            // 64
    float* b_a1s = b_p2s + 64;            // 256
    float* b_a2s = b_a1s + 256;           // 64
    float* b_fcs = b_a2s + 64;            // 64
    float* w_p1s = b_fcs + 64;            // 192
    int*   sidx  = (int*)(w_p1s + 192);   // 128
    float* stage  = (float*)t1hi;         // 8 x 1056 = 8448 f32 (<= 9216 u32)
    float* scores = (float*)h2hi;         // 128 x 65 = 8320 f32 (<= 9216 u32)

    int tid = threadIdx.x;
    int lane = tid & 31;
    int wid = tid >> 5;
    int g4 = lane >> 2, t4 = lane & 3;
    int mt = wid >> 1, hf = wid & 1;      // MLP-chain mapping
    int mtp = wid >> 1, nh = wid & 1;     // p2-MMA mapping (same split)

    // ---- weight prep: bf16 split + fragment swizzle (once) ----
    for (int i = tid; i < 8192; i += 512) {
        int kp = i >> 8, n = i & 255;
        u32 hi, lo;
        split2(w_a1[(2*kp)*256 + n], w_a1[(2*kp+1)*256 + n], hi, lo);
        int dst = kp*256 + (n ^ ((kp & 3) << 3));
        w1hi[dst] = hi; w1lo[dst] = lo;
    }
    for (int i = tid; i < 8192; i += 512) {
        int kp = i >> 6, n = i & 63;
        u32 hi, lo;
        split2(w_a2[(2*kp)*64 + n], w_a2[(2*kp+1)*64 + n], hi, lo);
        int dst = kp*64 + (n ^ ((kp & 3) << 3));
        w2hi[dst] = hi; w2lo[dst] = lo;
    }
    for (int i = tid; i < 2048; i += 512) {
        int kp = i >> 6, n = i & 63;
        u32 hi, lo;
        split2(w_p2[(2*kp)*64 + n], w_p2[(2*kp+1)*64 + n], hi, lo);
        int dst = kp*64 + (n ^ ((kp & 3) << 3));
        w2phi[dst] = hi; w2plo[dst] = lo;
    }
    if (tid < 192) w_p1s[tid] = w_p1[tid];
    if (tid < 256) b_a1s[tid] = b_a1[tid];
    if (tid < 64) {
        b_p1s[tid] = b_p1[tid]; b_p2s[tid] = b_p2[tid];
        b_a2s[tid] = b_a2[tid]; b_fcs[tid] = b_fc[tid];
    }
    float accY = 0.0f, accY2 = 0.0f;
    __syncthreads();

    for (int g = blockIdx.x; g < NPTS/PTS; g += ATTN_GRID) {
        int pbase = g * PTS;
        int bofs = (pbase >> 12) << 12;

        // ---- A: per-point loads
        if (tid < 128) sidx[tid] = g_idx[pbase*KK + tid];
        {
            int l = tid >> 6, d = tid & 63;
            qs[tid] = g_qkv[(size_t)(pbase + l)*192 + d];
        }
        if (tid < 24) {
            int l = tid / 3, c = tid - l*3;
            p0s[l*4 + c] = pos[(size_t)(pbase + l)*3 + c];
        }
        __syncthreads();

        // ---- B: rel
        if (tid < 384) {
            int r = tid / 3, c = tid - r*3;
            int l = r >> 4;
            rel[tid] = p0s[l*4 + c] - pos[(size_t)(bofs + sidx[r])*3 + c];
        }
        __syncthreads();

        // ---- C: pos-MLP -> t1 (bf16 split tiles)
#pragma unroll
        for (int e = 0; e < 8; e++) {
            int i = tid + e*512;              // 4096 pairs
            int r = i >> 5, kp = i & 31;
            int pp = kp*2;
            float r0v = rel[r*3+0], r1v = rel[r*3+1], r2v = rel[r*3+2];
            float a0 = b_p1s[pp];
            a0 = fmaf(r0v, w_p1s[pp],        a0);
            a0 = fmaf(r1v, w_p1s[64 + pp],   a0);
            a0 = fmaf(r2v, w_p1s[128 + pp],  a0);
            float a1 = b_p1s[pp+1];
            a1 = fmaf(r0v, w_p1s[pp+1],      a1);
            a1 = fmaf(r1v, w_p1s[64 + pp+1], a1);
            a1 = fmaf(r2v, w_p1s[128 + pp+1],a1);
            a0 = fmaxf(a0, 0.0f); a1 = fmaxf(a1, 0.0f);
            u32 hi, lo;
            split2(a0, a1, hi, lo);
            t1hi[r*H2P + kp] = hi;
            t1lo[r*H2P + kp] = lo;
        }
        __syncthreads();

        // ---- D: p2 on MMA (hi/lo chains split for ILP) + qk gather -> h2
        {
            u32 pahi[16], palo[16];
            int rowA = mtp*16 + g4;
#pragma unroll
            for (int ks = 0; ks < 4; ks++) {
                int c = ks*8 + t4;
                pahi[ks*4+0] = t1hi[rowA*H2P + c];
                pahi[ks*4+1] = t1hi[(rowA+8)*H2P + c];
                pahi[ks*4+2] = t1hi[rowA*H2P + c + 4];
                pahi[ks*4+3] = t1hi[(rowA+8)*H2P + c + 4];
                palo[ks*4+0] = t1lo[rowA*H2P + c];
                palo[ks*4+1] = t1lo[(rowA+8)*H2P + c];
                palo[ks*4+2] = t1lo[rowA*H2P + c + 4];
                palo[ks*4+3] = t1lo[(rowA+8)*H2P + c + 4];
            }
            float cP[16], cQ[16];
#pragma unroll
            for (int z = 0; z < 16; z++) { cP[z] = 0.0f; cQ[z] = 0.0f; }
#pragma unroll
            for (int ntl = 0; ntl < 4; ntl++) {
                int nsw = (nh*32 + ntl*8 + g4) ^ (t4 << 3);
#pragma unroll
                for (int ks = 0; ks < 4; ks++) {
                    int kp0 = ks*8 + t4;
                    u32 bh0 = w2phi[kp0*64 + nsw];
                    u32 bh1 = w2phi[(kp0+4)*64 + nsw];
                    u32 bl0 = w2plo[kp0*64 + nsw];
                    u32 bl1 = w2plo[(kp0+4)*64 + nsw];
                    mma16816(&cP[ntl*4], &pahi[ks*4], bh0, bh1);   // hh chain
                    mma16816(&cQ[ntl*4], &pahi[ks*4], bl0, bl1);   // hl+lh chain
                    mma16816(&cQ[ntl*4], &palo[ks*4], bh0, bh1);
                }
            }
            int r1 = mtp*16 + g4, r2 = r1 + 8;
            const float* krow1 = g_qkv + (size_t)(bofs + sidx[r1])*192 + 64;
            const float* krow2 = g_qkv + (size_t)(bofs + sidx[r2])*192 + 64;
#pragma unroll
            for (int ntl = 0; ntl < 4; ntl++) {
                int cb = nh*32 + ntl*8 + t4*2;
                float2 k1 = *(const float2*)&krow1[cb];
                float2 k2 = *(const float2*)&krow2[cb];
                float2 q1 = *(const float2*)&qs[mtp*64 + cb];
                float bb0 = b_p2s[cb], bb1 = b_p2s[cb+1];
                float h10 = (q1.x - k1.x) + (cP[ntl*4+0] + cQ[ntl*4+0]) + bb0;
                float h11 = (q1.y - k1.y) + (cP[ntl*4+1] + cQ[ntl*4+1]) + bb1;
                float h20 = (q1.x - k2.x) + (cP[ntl*4+2] + cQ[ntl*4+2]) + bb0;
                float h21 = (q1.y - k2.y) + (cP[ntl*4+3] + cQ[ntl*4+3]) + bb1;
                int kp = cb >> 1;
                u32 hi, lo;
                split2(h10, h11, hi, lo);
                h2hi[r1*H2P + kp] = hi; h2lo[r1*H2P + kp] = lo;
                split2(h20, h21, hi, lo);
                h2hi[r2*H2P + kp] = hi; h2lo[r2*H2P + kp] = lo;
            }
        }
        __syncthreads();

        // ---- E: load A1 fragments (h2) for this warp's m-tile
        u32 ahi[16], alo[16];
        {
            int rowA = mt*16 + g4;
#pragma unroll
            for (int ks = 0; ks < 4; ks++) {
                int c = ks*8 + t4;
                ahi[ks*4+0] = h2hi[rowA*H2P + c];
                ahi[ks*4+1] = h2hi[(rowA+8)*H2P + c];
                ahi[ks*4+2] = h2hi[rowA*H2P + c + 4];
                ahi[ks*4+3] = h2hi[(rowA+8)*H2P + c + 4];
                alo[ks*4+0] = h2lo[rowA*H2P + c];
                alo[ks*4+1] = h2lo[(rowA+8)*H2P + c];
                alo[ks*4+2] = h2lo[rowA*H2P + c + 4];
                alo[ks*4+3] = h2lo[(rowA+8)*H2P + c + 4];
            }
        }

        // ---- F: chunked attn MLP on tensor cores (sync-free)
        float C2[32];
#pragma unroll
        for (int z = 0; z < 32; z++) C2[z] = 0.0f;

#pragma unroll
        for (int jc = 0; jc < 4; jc++) {
            u32 s2hi[8], s2lo[8];
#pragma unroll
            for (int u = 0; u < 2; u++) {
                float cA[4] = {0,0,0,0}, cB[4] = {0,0,0,0};
                float cAq[4] = {0,0,0,0}, cBq[4] = {0,0,0,0};
                int nbase = jc*64 + hf*32 + u*16;
                int nswA = (nbase + g4) ^ (t4 << 3);
                int nswB = (nbase + 8 + g4) ^ (t4 << 3);
#pragma unroll
                for (int ks = 0; ks < 4; ks++) {
                    int kp0 = ks*8 + t4;
                    u32 bh0 = w1hi[kp0*256 + nswA];
                    u32 bh1 = w1hi[(kp0+4)*256 + nswA];
                    u32 bl0 = w1lo[kp0*256 + nswA];
                    u32 bl1 = w1lo[(kp0+4)*256 + nswA];
                    mma16816(cA,  &ahi[ks*4], bh0, bh1);
                    mma16816(cAq, &ahi[ks*4], bl0, bl1);
                    mma16816(cAq, &alo[ks*4], bh0, bh1);
                    u32 ch0 = w1hi[kp0*256 + nswB];
                    u32 ch1 = w1hi[(kp0+4)*256 + nswB];
                    u32 cl0 = w1lo[kp0*256 + nswB];
                    u32 cl1 = w1lo[(kp0+4)*256 + nswB];
                    mma16816(cB,  &ahi[ks*4], ch0, ch1);
                    mma16816(cBq, &ahi[ks*4], cl0, cl1);
                    mma16816(cBq, &alo[ks*4], ch0, ch1);
                }
                int cb = nbase + t4*2;
                float bA0 = b_a1s[cb],   bA1 = b_a1s[cb+1];
                float bB0 = b_a1s[cb+8], bB1 = b_a1s[cb+9];
                float sA0 = fmaxf((cA[0] + cAq[0]) + bA0, 0.0f);
                float sA1 = fmaxf((cA[1] + cAq[1]) + bA1, 0.0f);
                float sA2 = fmaxf((cA[2] + cAq[2]) + bA0, 0.0f);
                float sA3 = fmaxf((cA[3] + cAq[3]) + bA1, 0.0f);
                float sB0 = fmaxf((cB[0] + cBq[0]) + bB0, 0.0f);
                float sB1 = fmaxf((cB[1] + cBq[1]) + bB1, 0.0f);
                float sB2 = fmaxf((cB[2] + cBq[2]) + bB0, 0.0f);
                float sB3 = fmaxf((cB[3] + cBq[3]) + bB1, 0.0f);
                split2(sA0, sA1, s2hi[u*4+0], s2lo[u*4+0]);
                split2(sA2, sA3, s2hi[u*4+1], s2lo[u*4+1]);
                split2(sB0, sB1, s2hi[u*4+2], s2lo[u*4+2]);
                split2(sB2, sB3, s2hi[u*4+3], s2lo[u*4+3]);
            }
#pragma unroll
            for (int nt = 0; nt < 8; nt++) {
#pragma unroll
                for (int u = 0; u < 2; u++) {
                    int kp = jc*32 + hf*16 + u*8 + t4;
                    int nsw = (nt*8 + g4) ^ (t4 << 3);
                    u32 bh0 = w2hi[kp*64 + nsw];
                    u32 bh1 = w2hi[(kp+4)*64 + nsw];
                    u32 bl0 = w2lo[kp*64 + nsw];
                    u32 bl1 = w2lo[(kp+4)*64 + nsw];
                    mma16816(&C2[nt*4], &s2hi[u*4], bh0, bh1);
                    mma16816(&C2[nt*4], &s2hi[u*4], bl0, bl1);
                    mma16816(&C2[nt*4], &s2lo[u*4], bh0, bh1);
                }
            }
        }

        // ---- cross-half reduction of scores (stage in t1 region)
        if (hf) {
            float* sp = stage + mt*1056 + lane*33;
#pragma unroll
            for (int z = 0; z < 32; z++) sp[z] = C2[z];
        }
        __syncthreads();
        if (!hf) {
            float* sp = stage + mt*1056 + lane*33;
#pragma unroll
            for (int nt = 0; nt < 8; nt++) {
                int cb = nt*8 + t4*2;
                float v0 = C2[nt*4+0] + sp[nt*4+0] + b_a2s[cb];
                float v1 = C2[nt*4+1] + sp[nt*4+1] + b_a2s[cb+1];
                float v2 = C2[nt*4+2] + sp[nt*4+2] + b_a2s[cb];
                float v3 = C2[nt*4+3] + sp[nt*4+3] + b_a2s[cb+1];
                scores[(mt*16 + g4)*SCP + cb]         = v0;
                scores[(mt*16 + g4)*SCP + cb + 1]     = v1;
                scores[(mt*16 + g4 + 8)*SCP + cb]     = v2;
                scores[(mt*16 + g4 + 8)*SCP + cb + 1] = v3;
            }
        }
        __syncthreads();

        // ---- G: softmax over K + weighted v-sum (v from L2)
        {
            int l = tid >> 6, d = tid & 63;
            float vreg[16];
#pragma unroll
            for (int k = 0; k < 16; k++)
                vreg[k] = g_qkv[(size_t)(bofs + sidx[l*16 + k])*192 + 128 + d];
            float mx = -3.0e38f;
#pragma unroll
            for (int k = 0; k < 16; k++)
                mx = fmaxf(mx, scores[(l*16 + k)*SCP + d]);
            float ssum = 0.0f, a = 0.0f;
#pragma unroll
            for (int k = 0; k < 16; k++) {
                float e = __expf(scores[(l*16 + k)*SCP + d] - mx);
                ssum += e;
                a = fmaf(e, vreg[k], a);
            }
            aggs[tid] = a / ssum;
        }
        __syncthreads();

        // ---- H: fc (w_fc via L1/L2) + BN partials
        {
            int l = tid >> 6, d = tid & 63;
            float y = b_fcs[d];
#pragma unroll 8
            for (int c = 0; c < 64; c++)
                y = fmaf(aggs[l*64 + c], w_fc[c*64 + d], y);
            g_y[(size_t)(pbase + l)*64 + d] = y;
            accY += y;
            accY2 = fmaf(y, y, accY2);
        }
        __syncthreads();
    }

    // ---- reduce BN partials (t1 region as scratch)
    float* red = (float*)t1hi;
    red[tid] = accY;
    __syncthreads();
    if (tid < 64) {
        float s = 0.0f;
#pragma unroll
        for (int q = 0; q < 8; q++) s += red[q*64 + tid];
        g_part[blockIdx.x*128 + tid] = s;
    }
    __syncthreads();
    red[tid] = accY2;
    __syncthreads();
    if (tid < 64) {
        float s = 0.0f;
#pragma unroll
        for (int q = 0; q < 8; q++) s += red[q*64 + tid];
        g_part[blockIdx.x*128 + 64 + tid] = s;
    }
}

// ---------------- kernel 4: finish BN statistics ----------------------------
__global__ void bnstats_kernel() {
    __shared__ float sred[2048];
    int tid = threadIdx.x;            // 1024
    int d = tid & 63, q = tid >> 6;   // 16 groups
    float s = 0.0f, s2 = 0.0f;
    for (int blk = q; blk < ATTN_GRID; blk += 16) {
        s  += g_part[blk*128 + d];
        s2 += g_part[blk*128 + 64 + d];
    }
    sred[tid] = s; sred[1024 + tid] = s2;
    __syncthreads();
    if (tid < 64) {
        float ts = 0.0f, ts2 = 0.0f;
#pragma unroll
        for (int k = 0; k < 16; k++) {
            ts  += sred[k*64 + d];
            ts2 += sred[1024 + k*64 + d];
        }
        float mean = ts / (float)NPTS;
        float var  = ts2 / (float)NPTS - mean*mean;
        g_mv[d]      = mean;
        g_mv[64 + d] = rsqrtf(var + 1e-5f);
    }
}

// ---------------- kernel 5: BN apply + relu + residual ----------------------
__global__ void final_kernel(const float* __restrict__ x,
                             const float* __restrict__ gamma,
                             const float* __restrict__ beta,
                             float* __restrict__ out) {
    int i = blockIdx.x * blockDim.x + threadIdx.x;
    if (i < NPTS*DD) {
        int d = i & 63;
        float yv = (g_y[i] - g_mv[d]) * g_mv[64 + d] * gamma[d] + beta[d];
        out[i] = fmaxf(yv, 0.0f) + x[i];
    }
}

// ---------------- launch -----------------------------------------------------
extern "C" void kernel_launch(void* const* d_in, const int* in_sizes, int n_in,
                              void* d_out, int out_size) {
    const float* x     = (const float*)d_in[0];
    const float* pos   = (const float*)d_in[1];
    const float* w_qkv = (const float*)d_in[2];
    const float* b_qkv = (const float*)d_in[3];
    const float* w_p1  = (const float*)d_in[4];
    const float* b_p1  = (const float*)d_in[5];
    const float* w_p2  = (const float*)d_in[6];
    const float* b_p2  = (const float*)d_in[7];
    const float* w_a1  = (const float*)d_in[8];
    const float* b_a1  = (const float*)d_in[9];
    const float* w_a2  = (const float*)d_in[10];
    const float* b_a2  = (const float*)d_in[11];
    const float* w_fc  = (const float*)d_in[12];
    const float* b_fc  = (const float*)d_in[13];
    const float* gamma = (const float*)d_in[14];
    const float* beta  = (const float*)d_in[15];
    float* out = (float*)d_out;

    const int smem_qkv  = (64*192 + 64*64) * 4;
    const int smem_attn = (8192*4 + 2048*2 + 4608*4
                           + 512 + 32 + 384 + 512
                           + 64 + 64 + 256 + 64 + 64 + 192 + 128) * 4;  // 230272 B

    cudaFuncSetAttribute(qkv_kernel,  cudaFuncAttributeMaxDynamicSharedMemorySize, smem_qkv);
    cudaFuncSetAttribute(attn_kernel, cudaFuncAttributeMaxDynamicSharedMemorySize, smem_attn);

    bincount_kernel<<<NPTS/256, 256>>>(pos);            // 0
    binprefix_kernel<<<1, 1024>>>();                    // 1
    binscatter_kernel<<<NPTS/256, 256>>>(pos);          // 2
    knn_kernel<<<NPTS/8, 256>>>(pos);                   // 3 <- ncu capture slot
    qkv_kernel<<<NPTS/64, 192, smem_qkv>>>(x, w_qkv, b_qkv);
    attn_kernel<<<ATTN_GRID, 512, smem_attn>>>(pos, w_p1, b_p1, w_p2, b_p2,
                                               w_a1, b_a1, w_a2, b_a2, w_fc, b_fc);
    bnstats_kernel<<<1, 1024>>>();
    final_kernel<<<(NPTS*DD + 255)/256, 256>>>(x, gamma, beta, out);
}

// round 16
// speedup vs baseline: 1.0452x; 1.0056x over previous
#include <cuda_runtime.h>
#include <cuda_bf16.h>
#include <math.h>

#define BB 2
#define NN 4096
#define DD 64
#define HH 256
#define KK 16
#define NPTS (BB*NN)
#define ATTN_GRID 148
#define PTS 8               // points per iteration
#define ROWS 128            // PTS * KK rows
#define H2P 36              // packed bf16x2 row stride (u32)
#define SCP 65              // scores row stride

#define KNN_CAP 128
#define BIGD 3.0e38f

typedef unsigned long long u64;
typedef unsigned int u32;

// split two fp32 into packed bf16x2 hi and lo parts (x0 -> low half).
__device__ __forceinline__ void split2(float x0, float x1, u32& hi, u32& lo) {
    u32 h;
    asm("cvt.rn.bf16x2.f32 %0, %1, %2;" : "=r"(h) : "f"(x1), "f"(x0));
    float h0 = __uint_as_float(h << 16);
    float h1 = __uint_as_float(h & 0xffff0000u);
    u32 l;
    asm("cvt.rn.bf16x2.f32 %0, %1, %2;" : "=r"(l) : "f"(x1 - h1), "f"(x0 - h0));
    hi = h; lo = l;
}

__device__ __forceinline__ void mma16816(float* c, const u32* a, u32 b0, u32 b1) {
    asm volatile(
        "mma.sync.aligned.m16n8k16.row.col.f32.bf16.bf16.f32 "
        "{%0,%1,%2,%3}, {%4,%5,%6,%7}, {%8,%9}, {%0,%1,%2,%3};"
        : "+f"(c[0]), "+f"(c[1]), "+f"(c[2]), "+f"(c[3])
        : "r"(a[0]), "r"(a[1]), "r"(a[2]), "r"(a[3]), "r"(b0), "r"(b1));
}

// ---------------- scratch ----------------------------------------------------
__device__ float g_qkv[NPTS*192];
__device__ int   g_idx[NPTS*KK];
__device__ float g_y[NPTS*DD];
__device__ float g_part[ATTN_GRID*2*DD];
__device__ float g_mv[2*DD];
__device__ int   g_cellcnt[1024];
__device__ int   g_cellstart[1025];
__device__ int   g_cellcur[1024];
__device__ float4 g_posb[NPTS];

// ---------------- binning kernels --------------------------------------------
__device__ __forceinline__ int cell_of(float x, float y, float z, int b) {
    int cx = min(7, max(0, (int)(x * 8.0f)));
    int cy = min(7, max(0, (int)(y * 8.0f)));
    int cz = min(7, max(0, (int)(z * 8.0f)));
    return b*512 + cz*64 + cy*8 + cx;
}

__global__ void bincount_kernel(const float* __restrict__ pos) {
    int i = blockIdx.x*blockDim.x + threadIdx.x;
    if (i < NPTS) {
        float x = pos[(size_t)i*3], y = pos[(size_t)i*3+1], z = pos[(size_t)i*3+2];
        atomicAdd(&g_cellcnt[cell_of(x, y, z, i >> 12)], 1);
    }
}

__global__ void binprefix_kernel() {
    __shared__ int sh[1024];
    int tid = threadIdx.x;
    int c = g_cellcnt[tid];
    sh[tid] = c;
    for (int off = 1; off < 1024; off <<= 1) {
        __syncthreads();
        int v = (tid >= off) ? sh[tid - off] : 0;
        __syncthreads();
        sh[tid] += v;
    }
    int excl = sh[tid] - c;
    g_cellstart[tid] = excl;
    g_cellcur[tid] = excl;
    if (tid == 1023) g_cellstart[1024] = sh[tid];
}

__global__ void binscatter_kernel(const float* __restrict__ pos) {
    int i = blockIdx.x*blockDim.x + threadIdx.x;
    if (i < 1024) g_cellcnt[i] = 0;
    if (i < NPTS) {
        float x = pos[(size_t)i*3], y = pos[(size_t)i*3+1], z = pos[(size_t)i*3+2];
        int slot = atomicAdd(&g_cellcur[cell_of(x, y, z, i >> 12)], 1);
        g_posb[slot] = make_float4(x, y, z, __int_as_float(i & 4095));
    }
}

// ---------------- kernel 2: KNN (flattened phase-1, MLP=8 loads) -------------
__device__ __forceinline__ bool lexless(float d1, int i1, float d2, int i2) {
    return (d1 < d2) || (d1 == d2 && i1 < i2);
}

__device__ __forceinline__ void knn_flush(
    float& tD, int& tI, float& thrD, int& thrI, float& thr2,
    int& cnt, const float* bD, const int* bI, int lane)
{
    float e0 = (lane < 16) ? tD : BIGD;
    int   q0 = (lane < 16) ? tI : 0x7fffffff;
    float e1 = (lane      < cnt) ? bD[lane]      : BIGD;
    int   q1 = (lane      < cnt) ? bI[lane]      : 0x7fffffff;
    float e2 = (lane + 32 < cnt) ? bD[lane + 32] : BIGD;
    int   q2 = (lane + 32 < cnt) ? bI[lane + 32] : 0x7fffffff;
    float e3 = (lane + 64 < cnt) ? bD[lane + 64] : BIGD;
    int   q3 = (lane + 64 < cnt) ? bI[lane + 64] : 0x7fffffff;
    float e4 = (lane + 96 < cnt) ? bD[lane + 96] : BIGD;
    int   q4 = (lane + 96 < cnt) ? bI[lane + 96] : 0x7fffffff;

    float nD = BIGD; int nI = 0x7fffffff;
#pragma unroll
    for (int r = 0; r < 16; r++) {
        float md = e0; int mi = q0; int ms = 0;
        if (lexless(e1, q1, md, mi)) { md = e1; mi = q1; ms = 1; }
        if (lexless(e2, q2, md, mi)) { md = e2; mi = q2; ms = 2; }
        if (lexless(e3, q3, md, mi)) { md = e3; mi = q3; ms = 3; }
        if (lexless(e4, q4, md, mi)) { md = e4; mi = q4; ms = 4; }
        int src = (lane << 3) | ms;
#pragma unroll
        for (int off = 16; off; off >>= 1) {
            float od = __shfl_xor_sync(0xffffffffu, md, off);
            int   oi = __shfl_xor_sync(0xffffffffu, mi, off);
            int   os = __shfl_xor_sync(0xffffffffu, src, off);
            if (lexless(od, oi, md, mi)) { md = od; mi = oi; src = os; }
        }
        if (lane == (src >> 3)) {
            int sl = src & 7;
            if (sl == 0)      { e0 = BIGD; q0 = 0x7fffffff; }
            else if (sl == 1) { e1 = BIGD; q1 = 0x7fffffff; }
            else if (sl == 2) { e2 = BIGD; q2 = 0x7fffffff; }
            else if (sl == 3) { e3 = BIGD; q3 = 0x7fffffff; }
            else              { e4 = BIGD; q4 = 0x7fffffff; }
        }
        if (lane == r) { nD = md; nI = mi; }
    }
    tD = nD; tI = nI;
    thrD = __shfl_sync(0xffffffffu, nD, 15);
    thrI = __shfl_sync(0xffffffffu, nI, 15);
    thr2 = __fmul_rn(__fmul_rn(thrD, thrD), 1.0000005f);
    cnt = 0;
}

#define KNN_RUN(rowbase, x0v, x1v) do {                                         \
    int s_ = cstart[(rowbase) + (x0v)];                                         \
    int e_ = cstart[(rowbase) + (x1v) + 1];                                     \
    for (int i0 = s_; i0 < e_; i0 += 32) {                                      \
        int j = i0 + lane;                                                      \
        bool push = false; float dv = 0.0f; int ci = 0;                         \
        if (j < e_) {                                                           \
            float4 p = g_posb[j];                                               \
            float dx = px - p.x, dy = py - p.y, dz = pz - p.z;                  \
            float d2 = __fadd_rn(__fadd_rn(__fmul_rn(dx,dx), __fmul_rn(dy,dy)), \
                                 __fmul_rn(dz,dz));                             \
            if (d2 <= thr2) {                                                   \
                dv = sqrtf(d2);                                                 \
                ci = __float_as_int(p.w);                                       \
                push = lexless(dv, ci, thrD, thrI);                             \
            }                                                                   \
        }                                                                       \
        u32 mask = __ballot_sync(0xffffffffu, push);                            \
        if (push) {                                                             \
            int pp = cnt + __popc(mask & ((1u << lane) - 1u));                  \
            bD[pp] = dv; bI[pp] = ci;                                           \
        }                                                                       \
        cnt += __popc(mask);                                                    \
        if (cnt > KNN_CAP - 32)                                                 \
            knn_flush(tD, tI, thrD, thrI, thr2, cnt, bD, bI, lane);             \
    }                                                                           \
} while (0)

__global__ __launch_bounds__(256)
void knn_kernel(const float* __restrict__ pos) {
    __shared__ int cstart[513];
    __shared__ float bufD[8*KNN_CAP];
    __shared__ int   bufI[8*KNN_CAP];
    int tid = threadIdx.x;
    int warp = tid >> 5, lane = tid & 31;
    int q = blockIdx.x * 8 + warp;
    int bq = q >> 12;
    for (int i = tid; i < 513; i += 256) cstart[i] = g_cellstart[bq*512 + i];
    __syncthreads();

    float px = pos[(size_t)q*3 + 0];
    float py = pos[(size_t)q*3 + 1];
    float pz = pos[(size_t)q*3 + 2];
    int cx = min(7, max(0, (int)(px * 8.0f)));
    int cy = min(7, max(0, (int)(py * 8.0f)));
    int cz = min(7, max(0, (int)(pz * 8.0f)));
    float* bD = bufD + warp*KNN_CAP;
    int*   bI = bufI + warp*KNN_CAP;

    float tD = BIGD; int tI = 0x7fff0000 + lane;
    float thrD = BIGD; int thrI = 0x7fffffff;
    float thr2 = __int_as_float(0x7f800000);
    int cnt = 0;

    // ---- phase 1: flattened 3x3x3 scan with batched loads (MLP=8)
    {
        int segS[9], pre[10];
        pre[0] = 0;
        int x0 = max(cx-1, 0), x1 = min(cx+1, 7);
        int si = 0;
#pragma unroll
        for (int dz = -1; dz <= 1; dz++) {
#pragma unroll
            for (int dy = -1; dy <= 1; dy++) {
                int z = cz + dz, y = cy + dy;
                bool v = (z >= 0) && (z <= 7) && (y >= 0) && (y <= 7);
                int rowbase = z*64 + y*8;
                int s = v ? cstart[rowbase + x0] : 0;
                int e = v ? cstart[rowbase + x1 + 1] : 0;
                segS[si] = s;
                pre[si+1] = pre[si] + (e - s);
                si++;
            }
        }
        int total = pre[9];
        for (int base = 0; base < total; base += 256) {
            float4 pv[8];
            int fl[8];
#pragma unroll
            for (int w = 0; w < 8; w++) {
                int flat = base + w*32 + lane;
                fl[w] = flat;
                int r = 0;
#pragma unroll
                for (int j = 1; j < 9; j++) r = (flat >= pre[j]) ? j : r;
                int addr = segS[r] + (flat - pre[r]);
                if (flat >= total) addr = segS[r];       // clamped dummy (valid slot)
                pv[w] = g_posb[addr];                     // 8 independent loads
            }
#pragma unroll
            for (int w = 0; w < 8; w++) {
                bool push = false; float dv = 0.0f; int ci = 0;
                if (fl[w] < total) {
                    float dx = px - pv[w].x, dy = py - pv[w].y, dz = pz - pv[w].z;
                    float d2 = __fadd_rn(__fadd_rn(__fmul_rn(dx,dx), __fmul_rn(dy,dy)),
                                         __fmul_rn(dz,dz));
                    if (d2 <= thr2) {
                        dv = sqrtf(d2);
                        ci = __float_as_int(pv[w].w);
                        push = lexless(dv, ci, thrD, thrI);
                    }
                }
                u32 mask = __ballot_sync(0xffffffffu, push);
                if (push) {
                    int pp = cnt + __popc(mask & ((1u << lane) - 1u));
                    bD[pp] = dv; bI[pp] = ci;
                }
                cnt += __popc(mask);
                if (cnt > KNN_CAP - 32)
                    knn_flush(tD, tI, thrD, thrI, thr2, cnt, bD, bI, lane);
            }
        }
        if (cnt) knn_flush(tD, tI, thrD, thrI, thr2, cnt, bD, bI, lane);
    }

    // ---- phase 2: rings R>=2 until certified (rare)
    if (!(thrD < 0.125f * 0.999999f)) {
        for (int R = 2; R < 8; R++) {
            int zlo = max(cz - R, 0), zhi = min(cz + R, 7);
            for (int z = zlo; z <= zhi; z++) {
                int adz = (z > cz) ? (z - cz) : (cz - z);
                int ylo = max(cy - R, 0), yhi = min(cy + R, 7);
                for (int y = ylo; y <= yhi; y++) {
                    int ady = (y > cy) ? (y - cy) : (cy - y);
                    int rowbase = z*64 + y*8;
                    if (adz == R || ady == R) {
                        int x0 = max(cx - R, 0), x1 = min(cx + R, 7);
                        KNN_RUN(rowbase, x0, x1);
                    } else {
                        if (cx - R >= 0) KNN_RUN(rowbase, cx - R, cx - R);
                        if (cx + R <= 7) KNN_RUN(rowbase, cx + R, cx + R);
                    }
                }
            }
            if (cnt) knn_flush(tD, tI, thrD, thrI, thr2, cnt, bD, bI, lane);
            if (thrD < (float)R * 0.125f * 0.999999f) break;
        }
    }

    if (lane < 16) g_idx[q*KK + lane] = tI;
}

// ---------------- kernel 1: QKV GEMM  (8192x64 @ 64x192) -------------------
__global__ void qkv_kernel(const float* __restrict__ x,
                           const float* __restrict__ w,
                           const float* __restrict__ bq) {
    extern __shared__ float sm[];
    float* ws = sm;
    float* xs = sm + 64*192;
    int tid = threadIdx.x;
    for (int i = tid; i < 64*192; i += 192) ws[i] = w[i];
    int row0 = blockIdx.x * 64;
    for (int i = tid; i < 64*64; i += 192) xs[i] = x[row0*64 + i];
    __syncthreads();
    float bb = bq[tid];
    for (int r0 = 0; r0 < 64; r0 += 8) {
        float acc[8];
#pragma unroll
        for (int r = 0; r < 8; r++) acc[r] = bb;
        for (int i = 0; i < 64; i++) {
            float wv = ws[i*192 + tid];
#pragma unroll
            for (int r = 0; r < 8; r++) acc[r] = fmaf(xs[(r0+r)*64 + i], wv, acc[r]);
        }
#pragma unroll
        for (int r = 0; r < 8; r++) g_qkv[(row0 + r0 + r)*192 + tid] = acc[r];
    }
}

// ---------------- kernel 3: fused attn (all GEMMs on tensor cores) ----------
__global__ __launch_bounds__(512, 1)
void attn_kernel(const float* __restrict__ pos,
                 const float* __restrict__ w_p1, const float* __restrict__ b_p1,
                 const float* __restrict__ w_p2, const float* __restrict__ b_p2,
                 const float* __restrict__ w_a1, const float* __restrict__ b_a1,
                 const float* __restrict__ w_a2, const float* __restrict__ b_a2,
                 const float* __restrict__ w_fc, const float* __restrict__ b_fc) {
    extern __shared__ float sm[];
    u32* w1hi  = (u32*)sm;
    u32* w1lo  = w1hi + 8192;
    u32* w2hi  = w1lo + 8192;
    u32* w2lo  = w2hi + 8192;
    u32* w2phi = w2lo + 8192;
    u32* w2plo = w2phi + 2048;
    u32* t1hi  = w2plo + 2048;
    u32* t1lo  = t1hi + 4608;
    u32* h2hi  = t1lo + 4608;
    u32* h2lo  = h2hi + 4608;
    float* qs    = (float*)(h2lo + 4608);
    float* p0s   = qs + 512;
    float* rel   = p0s + 32;
    float* aggs  = rel + 384;
    float* b_p1s = aggs + 512;
    float* b_p2s = b_p1s + 64;
    float* b_a1s = b_p2s + 64;
    float* b_a2s = b_a1s + 256;
    float* b_fcs = b_a2s + 64;
    float* w_p1s = b_fcs + 64;
    int*   sidx  = (int*)(w_p1s + 192);
    float* stage  = (float*)t1hi;
    float* scores = (float*)h2hi;

    int tid = threadIdx.x;
    int lane = tid & 31;
    int wid = tid >> 5;
    int g4 = lane >> 2, t4 = lane & 3;
    int mt = wid >> 1, hf = wid & 1;
    int mtp = wid >> 1, nh = wid & 1;

    for (int i = tid; i < 8192; i += 512) {
        int kp = i >> 8, n = i & 255;
        u32 hi, lo;
        split2(w_a1[(2*kp)*256 + n], w_a1[(2*kp+1)*256 + n], hi, lo);
        int dst = kp*256 + (n ^ ((kp & 3) << 3));
        w1hi[dst] = hi; w1lo[dst] = lo;
    }
    for (int i = tid; i < 8192; i += 512) {
        int kp = i >> 6, n = i & 63;
        u32 hi, lo;
        split2(w_a2[(2*kp)*64 + n], w_a2[(2*kp+1)*64 + n], hi, lo);
        int dst = kp*64 + (n ^ ((kp & 3) << 3));
        w2hi[dst] = hi; w2lo[dst] = lo;
    }
    for (int i = tid; i < 2048; i += 512) {
        int kp = i >> 6, n = i & 63;
        u32 hi, lo;
        split2(w_p2[(2*kp)*64 + n], w_p2[(2*kp+1)*64 + n], hi, lo);
        int dst = kp*64 + (n ^ ((kp & 3) << 3));
        w2phi[dst] = hi; w2plo[dst] = lo;
    }
    if (tid < 192) w_p1s[tid] = w_p1[tid];
    if (tid < 256) b_a1s[tid] = b_a1[tid];
    if (tid < 64) {
        b_p1s[tid] = b_p1[tid]; b_p2s[tid] = b_p2[tid];
        b_a2s[tid] = b_a2[tid]; b_fcs[tid] = b_fc[tid];
    }
    float accY = 0.0f, accY2 = 0.0f;
    __syncthreads();

    for (int g = blockIdx.x; g < NPTS/PTS; g += ATTN_GRID) {
        int pbase = g * PTS;
        int bofs = (pbase >> 12) << 12;

        if (tid < 128) sidx[tid] = g_idx[pbase*KK + tid];
        {
            int l = tid >> 6, d = tid & 63;
            qs[tid] = g_qkv[(size_t)(pbase + l)*192 + d];
        }
        if (tid < 24) {
            int l = tid / 3, c = tid - l*3;
            p0s[l*4 + c] = pos[(size_t)(pbase + l)*3 + c];
        }
        __syncthreads();

        if (tid < 384) {
            int r = tid / 3, c = tid - r*3;
            int l = r >> 4;
            rel[tid] = p0s[l*4 + c] - pos[(size_t)(bofs + sidx[r])*3 + c];
        }
        __syncthreads();

#pragma unroll
        for (int e = 0; e < 8; e++) {
            int i = tid + e*512;
            int r = i >> 5, kp = i & 31;
            int pp = kp*2;
            float r0v = rel[r*3+0], r1v = rel[r*3+1], r2v = rel[r*3+2];
            float a0 = b_p1s[pp];
            a0 = fmaf(r0v, w_p1s[pp],        a0);
            a0 = fmaf(r1v, w_p1s[64 + pp],   a0);
            a0 = fmaf(r2v, w_p1s[128 + pp],  a0);
            float a1 = b_p1s[pp+1];
            a1 = fmaf(r0v, w_p1s[pp+1],      a1);
            a1 = fmaf(r1v, w_p1s[64 + pp+1], a1);
            a1 = fmaf(r2v, w_p1s[128 + pp+1],a1);
            a0 = fmaxf(a0, 0.0f); a1 = fmaxf(a1, 0.0f);
            u32 hi, lo;
            split2(a0, a1, hi, lo);
            t1hi[r*H2P + kp] = hi;
            t1lo[r*H2P + kp] = lo;
        }
        __syncthreads();

        {
            u32 pahi[16], palo[16];
            int rowA = mtp*16 + g4;
#pragma unroll
            for (int ks = 0; ks < 4; ks++) {
                int c = ks*8 + t4;
                pahi[ks*4+0] = t1hi[rowA*H2P + c];
                pahi[ks*4+1] = t1hi[(rowA+8)*H2P + c];
                pahi[ks*4+2] = t1hi[rowA*H2P + c + 4];
                pahi[ks*4+3] = t1hi[(rowA+8)*H2P + c + 4];
                palo[ks*4+0] = t1lo[rowA*H2P + c];
                palo[ks*4+1] = t1lo[(rowA+8)*H2P + c];
                palo[ks*4+2] = t1lo[rowA*H2P + c + 4];
                palo[ks*4+3] = t1lo[(rowA+8)*H2P + c + 4];
            }
            float cP[16], cQ[16];
#pragma unroll
            for (int z = 0; z < 16; z++) { cP[z] = 0.0f; cQ[z] = 0.0f; }
#pragma unroll
            for (int ntl = 0; ntl < 4; ntl++) {
                int nsw = (nh*32 + ntl*8 + g4) ^ (t4 << 3);
#pragma unroll
                for (int ks = 0; ks < 4; ks++) {
                    int kp0 = ks*8 + t4;
                    u32 bh0 = w2phi[kp0*64 + nsw];
                    u32 bh1 = w2phi[(kp0+4)*64 + nsw];
                    u32 bl0 = w2plo[kp0*64 + nsw];
                    u32 bl1 = w2plo[(kp0+4)*64 + nsw];
                    mma16816(&cP[ntl*4], &pahi[ks*4], bh0, bh1);
                    mma16816(&cQ[ntl*4], &pahi[ks*4], bl0, bl1);
                    mma16816(&cQ[ntl*4], &palo[ks*4], bh0, bh1);
                }
            }
            int r1 = mtp*16 + g4, r2 = r1 + 8;
            const float* krow1 = g_qkv + (size_t)(bofs + sidx[r1])*192 + 64;
            const float* krow2 = g_qkv + (size_t)(bofs + sidx[r2])*192 + 64;
#pragma unroll
            for (int ntl = 0; ntl < 4; ntl++) {
                int cb = nh*32 + ntl*8 + t4*2;
                float2 k1 = *(const float2*)&krow1[cb];
                float2 k2 = *(const float2*)&krow2[cb];
                float2 q1 = *(const float2*)&qs[mtp*64 + cb];
                float bb0 = b_p2s[cb], bb1 = b_p2s[cb+1];
                float h10 = (q1.x - k1.x) + (cP[ntl*4+0] + cQ[ntl*4+0]) + bb0;
                float h11 = (q1.y - k1.y) + (cP[ntl*4+1] + cQ[ntl*4+1]) + bb1;
                float h20 = (q1.x - k2.x) + (cP[ntl*4+2] + cQ[ntl*4+2]) + bb0;
                float h21 = (q1.y - k2.y) + (cP[ntl*4+3] + cQ[ntl*4+3]) + bb1;
                int kp = cb >> 1;
                u32 hi, lo;
                split2(h10, h11, hi, lo);
                h2hi[r1*H2P + kp] = hi; h2lo[r1*H2P + kp] = lo;
                split2(h20, h21, hi, lo);
                h2hi[r2*H2P + kp] = hi; h2lo[r2*H2P + kp] = lo;
            }
        }
        __syncthreads();

        u32 ahi[16], alo[16];
        {
            int rowA = mt*16 + g4;
#pragma unroll
            for (int ks = 0; ks < 4; ks++) {
                int c = ks*8 + t4;
                ahi[ks*4+0] = h2hi[rowA*H2P + c];
                ahi[ks*4+1] = h2hi[(rowA+8)*H2P + c];
                ahi[ks*4+2] = h2hi[rowA*H2P + c + 4];
                ahi[ks*4+3] = h2hi[(rowA+8)*H2P + c + 4];
                alo[ks*4+0] = h2lo[rowA*H2P + c];
                alo[ks*4+1] = h2lo[(rowA+8)*H2P + c];
                alo[ks*4+2] = h2lo[rowA*H2P + c + 4];
                alo[ks*4+3] = h2lo[(rowA+8)*H2P + c + 4];
            }
        }

        float C2[32];
#pragma unroll
        for (int z = 0; z < 32; z++) C2[z] = 0.0f;

#pragma unroll
        for (int jc = 0; jc < 4; jc++) {
            u32 s2hi[8], s2lo[8];
#pragma unroll
            for (int u = 0; u < 2; u++) {
                float cA[4] = {0,0,0,0}, cB[4] = {0,0,0,0};
                float cAq[4] = {0,0,0,0}, cBq[4] = {0,0,0,0};
                int nbase = jc*64 + hf*32 + u*16;
                int nswA = (nbase + g4) ^ (t4 << 3);
                int nswB = (nbase + 8 + g4) ^ (t4 << 3);
#pragma unroll
                for (int ks = 0; ks < 4; ks++) {
                    int kp0 = ks*8 + t4;
                    u32 bh0 = w1hi[kp0*256 + nswA];
                    u32 bh1 = w1hi[(kp0+4)*256 + nswA];
                    u32 bl0 = w1lo[kp0*256 + nswA];
                    u32 bl1 = w1lo[(kp0+4)*256 + nswA];
                    mma16816(cA,  &ahi[ks*4], bh0, bh1);
                    mma16816(cAq, &ahi[ks*4], bl0, bl1);
                    mma16816(cAq, &alo[ks*4], bh0, bh1);
                    u32 ch0 = w1hi[kp0*256 + nswB];
                    u32 ch1 = w1hi[(kp0+4)*256 + nswB];
                    u32 cl0 = w1lo[kp0*256 + nswB];
                    u32 cl1 = w1lo[(kp0+4)*256 + nswB];
                    mma16816(cB,  &ahi[ks*4], ch0, ch1);
                    mma16816(cBq, &ahi[ks*4], cl0, cl1);
                    mma16816(cBq, &alo[ks*4], ch0, ch1);
                }
                int cb = nbase + t4*2;
                float bA0 = b_a1s[cb],   bA1 = b_a1s[cb+1];
                float bB0 = b_a1s[cb+8], bB1 = b_a1s[cb+9];
                float sA0 = fmaxf((cA[0] + cAq[0]) + bA0, 0.0f);
                float sA1 = fmaxf((cA[1] + cAq[1]) + bA1, 0.0f);
                float sA2 = fmaxf((cA[2] + cAq[2]) + bA0, 0.0f);
                float sA3 = fmaxf((cA[3] + cAq[3]) + bA1, 0.0f);
                float sB0 = fmaxf((cB[0] + cBq[0]) + bB0, 0.0f);
                float sB1 = fmaxf((cB[1] + cBq[1]) + bB1, 0.0f);
                float sB2 = fmaxf((cB[2] + cBq[2]) + bB0, 0.0f);
                float sB3 = fmaxf((cB[3] + cBq[3]) + bB1, 0.0f);
                split2(sA0, sA1, s2hi[u*4+0], s2lo[u*4+0]);
                split2(sA2, sA3, s2hi[u*4+1], s2lo[u*4+1]);
                split2(sB0, sB1, s2hi[u*4+2], s2lo[u*4+2]);
                split2(sB2, sB3, s2hi[u*4+3], s2lo[u*4+3]);
            }
#pragma unroll
            for (int nt = 0; nt < 8; nt++) {
#pragma unroll
                for (int u = 0; u < 2; u++) {
                    int kp = jc*32 + hf*16 + u*8 + t4;
                    int nsw = (nt*8 + g4) ^ (t4 << 3);
                    u32 bh0 = w2hi[kp*64 + nsw];
                    u32 bh1 = w2hi[(kp+4)*64 + nsw];
                    u32 bl0 = w2lo[kp*64 + nsw];
                    u32 bl1 = w2lo[(kp+4)*64 + nsw];
                    mma16816(&C2[nt*4], &s2hi[u*4], bh0, bh1);
                    mma16816(&C2[nt*4], &s2hi[u*4], bl0, bl1);
                    mma16816(&C2[nt*4], &s2lo[u*4], bh0, bh1);
                }
            }
        }

        if (hf) {
            float* sp = stage + mt*1056 + lane*33;
#pragma unroll
            for (int z = 0; z < 32; z++) sp[z] = C2[z];
        }
        __syncthreads();
        if (!hf) {
            float* sp = stage + mt*1056 + lane*33;
#pragma unroll
            for (int nt = 0; nt < 8; nt++) {
                int cb = nt*8 + t4*2;
                float v0 = C2[nt*4+0] + sp[nt*4+0] + b_a2s[cb];
                float v1 = C2[nt*4+1] + sp[nt*4+1] + b_a2s[cb+1];
                float v2 = C2[nt*4+2] + sp[nt*4+2] + b_a2s[cb];
                float v3 = C2[nt*4+3] + sp[nt*4+3] + b_a2s[cb+1];
                scores[(mt*16 + g4)*SCP + cb]         = v0;
                scores[(mt*16 + g4)*SCP + cb + 1]     = v1;
                scores[(mt*16 + g4 + 8)*SCP + cb]     = v2;
                scores[(mt*16 + g4 + 8)*SCP + cb + 1] = v3;
            }
        }
        __syncthreads();

        {
            int l = tid >> 6, d = tid & 63;
            float vreg[16];
#pragma unroll
            for (int k = 0; k < 16; k++)
                vreg[k] = g_qkv[(size_t)(bofs + sidx[l*16 + k])*192 + 128 + d];
            float mx = -3.0e38f;
#pragma unroll
            for (int k = 0; k < 16; k++)
                mx = fmaxf(mx, scores[(l*16 + k)*SCP + d]);
            float ssum = 0.0f, a = 0.0f;
#pragma unroll
            for (int k = 0; k < 16; k++) {
                float e = __expf(scores[(l*16 + k)*SCP + d] - mx);
                ssum += e;
                a = fmaf(e, vreg[k], a);
            }
            aggs[tid] = a / ssum;
        }
        __syncthreads();

        {
            int l = tid >> 6, d = tid & 63;
            float y = b_fcs[d];
#pragma unroll 8
            for (int c = 0; c < 64; c++)
                y = fmaf(aggs[l*64 + c], w_fc[c*64 + d], y);
            g_y[(size_t)(pbase + l)*64 + d] = y;
            accY += y;
            accY2 = fmaf(y, y, accY2);
        }
        __syncthreads();
    }

    float* red = (float*)t1hi;
    red[tid] = accY;
    __syncthreads();
    if (tid < 64) {
        float s = 0.0f;
#pragma unroll
        for (int q = 0; q < 8; q++) s += red[q*64 + tid];
        g_part[blockIdx.x*128 + tid] = s;
    }
    __syncthreads();
    red[tid] = accY2;
    __syncthreads();
    if (tid < 64) {
        float s = 0.0f;
#pragma unroll
        for (int q = 0; q < 8; q++) s += red[q*64 + tid];
        g_part[blockIdx.x*128 + 64 + tid] = s;
    }
}

// ---------------- kernel 4: finish BN statistics ----------------------------
__global__ void bnstats_kernel() {
    __shared__ float sred[2048];
    int tid = threadIdx.x;
    int d = tid & 63, q = tid >> 6;
    float s = 0.0f, s2 = 0.0f;
    for (int blk = q; blk < ATTN_GRID; blk += 16) {
        s  += g_part[blk*128 + d];
        s2 += g_part[blk*128 + 64 + d];
    }
    sred[tid] = s; sred[1024 + tid] = s2;
    __syncthreads();
    if (tid < 64) {
        float ts = 0.0f, ts2 = 0.0f;
#pragma unroll
        for (int k = 0; k < 16; k++) {
            ts  += sred[k*64 + d];
            ts2 += sred[1024 + k*64 + d];
        }
        float mean = ts / (float)NPTS;
        float var  = ts2 / (float)NPTS - mean*mean;
        g_mv[d]      = mean;
        g_mv[64 + d] = rsqrtf(var + 1e-5f);
    }
}

// ---------------- kernel 5: BN apply + relu + residual ----------------------
__global__ void final_kernel(const float* __restrict__ x,
                             const float* __restrict__ gamma,
                             const float* __restrict__ beta,
                             float* __restrict__ out) {
    int i = blockIdx.x * blockDim.x + threadIdx.x;
    if (i < NPTS*DD) {
        int d = i & 63;
        float yv = (g_y[i] - g_mv[d]) * g_mv[64 + d] * gamma[d] + beta[d];
        out[i] = fmaxf(yv, 0.0f) + x[i];
    }
}

// ---------------- launch -----------------------------------------------------
extern "C" void kernel_launch(void* const* d_in, const int* in_sizes, int n_in,
                              void* d_out, int out_size) {
    const float* x     = (const float*)d_in[0];
    const float* pos   = (const float*)d_in[1];
    const float* w_qkv = (const float*)d_in[2];
    const float* b_qkv = (const float*)d_in[3];
    const float* w_p1  = (const float*)d_in[4];
    const float* b_p1  = (const float*)d_in[5];
    const float* w_p2  = (const float*)d_in[6];
    const float* b_p2  = (const float*)d_in[7];
    const float* w_a1  = (const float*)d_in[8];
    const float* b_a1  = (const float*)d_in[9];
    const float* w_a2  = (const float*)d_in[10];
    const float* b_a2  = (const float*)d_in[11];
    const float* w_fc  = (const float*)d_in[12];
    const float* b_fc  = (const float*)d_in[13];
    const float* gamma = (const float*)d_in[14];
    const float* beta  = (const float*)d_in[15];
    float* out = (float*)d_out;

    const int smem_qkv  = (64*192 + 64*64) * 4;
    const int smem_attn = (8192*4 + 2048*2 + 4608*4
                           + 512 + 32 + 384 + 512
                           + 64 + 64 + 256 + 64 + 64 + 192 + 128) * 4;

    cudaFuncSetAttribute(qkv_kernel,  cudaFuncAttributeMaxDynamicSharedMemorySize, smem_qkv);
    cudaFuncSetAttribute(attn_kernel, cudaFuncAttributeMaxDynamicSharedMemorySize, smem_attn);

    bincount_kernel<<<NPTS/256, 256>>>(pos);            // 0
    binprefix_kernel<<<1, 1024>>>();                    // 1
    binscatter_kernel<<<NPTS/256, 256>>>(pos);          // 2
    knn_kernel<<<NPTS/8, 256>>>(pos);                   // 3 <- ncu capture slot
    qkv_kernel<<<NPTS/64, 192, smem_qkv>>>(x, w_qkv, b_qkv);
    attn_kernel<<<ATTN_GRID, 512, smem_attn>>>(pos, w_p1, b_p1, w_p2, b_p2,
                                               w_a1, b_a1, w_a2, b_a2, w_fc, b_fc);
    bnstats_kernel<<<1, 1024>>>();
    final_kernel<<<(NPTS*DD + 255)/256, 256>>>(x, gamma, beta, out);
}